// round 1
// baseline (speedup 1.0000x reference)
#include <cuda_runtime.h>
#include <math.h>

#define DIM   112
#define DIMO  224
#define MLPD  896
#define NPIX  (8*128*128)
#define NTOK  (8*64*64)

// Scratch (device globals; no allocation allowed)
__device__ float g_hs_ln[(size_t)NPIX * DIM];   // LN1 output, original layout
__device__ float g_hs[(size_t)NTOK * DIMO];     // residual + attn output ("hs")

// ---------------------------------------------------------------------------
// K1: LayerNorm over DIM=112, warp per pixel
// ---------------------------------------------------------------------------
__global__ void k_ln1(const float* __restrict__ x,
                      const float* __restrict__ g,
                      const float* __restrict__ b) {
    int pix  = blockIdx.x * 8 + (threadIdx.x >> 5);
    int lane = threadIdx.x & 31;
    const float* px = x + (size_t)pix * DIM;
    float v0 = px[lane], v1 = px[lane + 32], v2 = px[lane + 64];
    float v3 = (lane < 16) ? px[lane + 96] : 0.f;
    float s = v0 + v1 + v2 + v3;
    #pragma unroll
    for (int o = 16; o; o >>= 1) s += __shfl_xor_sync(~0u, s, o);
    float m = s * (1.f / 112.f);
    float d0 = v0 - m, d1 = v1 - m, d2 = v2 - m;
    float d3 = (lane < 16) ? v3 - m : 0.f;
    float q = d0*d0 + d1*d1 + d2*d2 + d3*d3;
    #pragma unroll
    for (int o = 16; o; o >>= 1) q += __shfl_xor_sync(~0u, q, o);
    float rs = rsqrtf(q * (1.f / 112.f) + 1e-6f);
    float* po = g_hs_ln + (size_t)pix * DIM;
    po[lane]      = d0 * rs * g[lane]      + b[lane];
    po[lane + 32] = d1 * rs * g[lane + 32] + b[lane + 32];
    po[lane + 64] = d2 * rs * g[lane + 64] + b[lane + 64];
    if (lane < 16) po[lane + 96] = d3 * rs * g[lane + 96] + b[lane + 96];
}

// ---------------------------------------------------------------------------
// K2: residual = maxpool2(hs_ln @ res_proj_w + b) -> g_hs
// Block: 224 threads, 8 output tokens (one row strip), register tile acc[32]
// ---------------------------------------------------------------------------
__global__ void k_res(const float* __restrict__ W,
                      const float* __restrict__ bias) {
    __shared__ float Xr[32][112];   // 2 rows x 16 cols x 112
    int t0  = blockIdx.x * 8;
    int b   = t0 >> 12;             // 4096 tokens/image
    int rem = t0 & 4095;
    int y2  = rem >> 6;
    int x2b = rem & 63;

    for (int e = threadIdx.x; e < 32 * 112; e += 224) {
        int p = e / 112, c = e - p * 112;
        int dy = p >> 4, xo = p & 15;
        int y = 2 * y2 + dy, x = 2 * x2b + xo;
        Xr[p][c] = g_hs_ln[(((size_t)b * 128 + y) * 128 + x) * 112 + c];
    }
    __syncthreads();

    int d = threadIdx.x;
    float acc[32];
    #pragma unroll
    for (int i = 0; i < 32; i++) acc[i] = 0.f;
    for (int c = 0; c < 112; c++) {
        float w = W[c * 224 + d];
        #pragma unroll
        for (int j = 0; j < 8; j++) {
            #pragma unroll
            for (int dy = 0; dy < 2; dy++)
                #pragma unroll
                for (int dx = 0; dx < 2; dx++)
                    acc[j * 4 + dy * 2 + dx] += Xr[dy * 16 + 2 * j + dx][c] * w;
        }
    }
    float bb = bias[d];
    #pragma unroll
    for (int j = 0; j < 8; j++) {
        float m = fmaxf(fmaxf(acc[j*4], acc[j*4+1]), fmaxf(acc[j*4+2], acc[j*4+3]));
        g_hs[(size_t)(t0 + j) * 224 + d] = m + bb;
    }
}

// ---------------------------------------------------------------------------
// K3: per-window attention. 2048 blocks x 448 threads, dynamic smem.
// smem: Xs 64x113 | Ks 64x225 | Vs 64x225 | Qs 16x225; scores alias Xs, O alias Qs
// ---------------------------------------------------------------------------
#define XS_N  (64 * 113)      // 7232
#define KS_N  (64 * 225)      // 14400
#define QS_N  (16 * 225)      // 3600
#define SMEM3 ((XS_N + 2 * KS_N + QS_N) * 4)

__global__ void k_attn(const float* __restrict__ Wqkv, const float* __restrict__ bqkv,
                       const float* __restrict__ Wp,   const float* __restrict__ bp) {
    extern __shared__ float sm[];
    float* Xs = sm;
    float* Ks = sm + XS_N;
    float* Vs = Ks + KS_N;
    float* Qs = Vs + KS_N;
    float* Sc = Xs;   // 4096 floats, alias (X dead after QKV)
    float* Os = Qs;   // alias (Q dead after scores)

    int wi = blockIdx.x;
    int b  = wi >> 8;
    int r  = wi & 255;
    int wy = r >> 4, wx = r & 15;
    int tid  = threadIdx.x;
    int d    = tid % 224;     // output-dim lane
    int half = tid / 224;     // 0/1 token-split

    // load window (64 tokens x 112)
    for (int e = tid; e < 64 * 112; e += 448) {
        int t = e / 112, c = e - t * 112;
        int ty = t >> 3, tx = t & 7;
        int y = wy * 8 + ty, x = wx * 8 + tx;
        Xs[t * 113 + c] = g_hs_ln[(((size_t)b * 128 + y) * 128 + x) * 112 + c];
    }
    __syncthreads();

    // K and V: each half does 2 token-tiles of 16 per matrix
    #pragma unroll
    for (int m = 0; m < 2; m++) {
        int off = 224 + m * 224;
        float* Out = m ? Vs : Ks;
        for (int tt = half * 32; tt < half * 32 + 32; tt += 16) {
            float acc[16];
            float bb = bqkv[off + d];
            #pragma unroll
            for (int i = 0; i < 16; i++) acc[i] = bb;
            for (int c = 0; c < 112; c++) {
                float w = Wqkv[c * 672 + off + d];
                #pragma unroll
                for (int i = 0; i < 16; i++) acc[i] += Xs[(tt + i) * 113 + c] * w;
            }
            #pragma unroll
            for (int i = 0; i < 16; i++) Out[(tt + i) * 225 + d] = acc[i];
        }
    }

    // Q with fused 2x2 token maxpool: half owns 8 q-cells, loops all 4 phases
    {
        int qbase = half * 8;
        float qmax[8];
        for (int p = 0; p < 4; p++) {
            int dy = p >> 1, dx = p & 1;
            float acc[8];
            float bb = bqkv[d];
            #pragma unroll
            for (int i = 0; i < 8; i++) acc[i] = bb;
            for (int c = 0; c < 112; c++) {
                float w = Wqkv[c * 672 + d];
                #pragma unroll
                for (int i = 0; i < 8; i++) {
                    int qc = qbase + i;
                    int qy = qc >> 2, qx = qc & 3;
                    int t = (2 * qy + dy) * 8 + 2 * qx + dx;
                    acc[i] += Xs[t * 113 + c] * w;
                }
            }
            #pragma unroll
            for (int i = 0; i < 8; i++)
                qmax[i] = (p == 0) ? acc[i] : fmaxf(qmax[i], acc[i]);
        }
        #pragma unroll
        for (int i = 0; i < 8; i++) Qs[(qbase + i) * 225 + d] = qmax[i];
    }
    __syncthreads();

    // scores: 4 heads x 16 q x 64 k, dot of 56; write into Sc (aliases Xs)
    const float scale = 0.13363062095621219f;   // 56^-0.5
    for (int e = tid; e < 4096; e += 448) {
        int h = e >> 10, qt = (e >> 6) & 15, kt = e & 63;
        const float* qp = Qs + qt * 225 + h * 56;
        const float* kp = Ks + kt * 225 + h * 56;
        float s = 0.f;
        #pragma unroll
        for (int hd = 0; hd < 56; hd++) s += qp[hd] * kp[hd];
        Sc[e] = s * scale;
    }
    __syncthreads();

    // softmax over 64 rows of 64 (warp per row)
    int warp = tid >> 5, lane = tid & 31;
    for (int rr = warp; rr < 64; rr += 14) {
        float* row = Sc + rr * 64;
        float a = row[lane], c2 = row[lane + 32];
        float mx = fmaxf(a, c2);
        #pragma unroll
        for (int o = 16; o; o >>= 1) mx = fmaxf(mx, __shfl_xor_sync(~0u, mx, o));
        a = __expf(a - mx); c2 = __expf(c2 - mx);
        float s = a + c2;
        #pragma unroll
        for (int o = 16; o; o >>= 1) s += __shfl_xor_sync(~0u, s, o);
        float inv = 1.f / s;
        row[lane] = a * inv; row[lane + 32] = c2 * inv;
    }
    __syncthreads();

    // O = P @ V  (write into Os, aliases Qs which is dead now)
    {
        int h = d / 56;
        int qbase = half * 8;
        const float* scb = Sc + h * 1024;
        float acc[8];
        #pragma unroll
        for (int i = 0; i < 8; i++) acc[i] = 0.f;
        for (int kt = 0; kt < 64; kt++) {
            float v = Vs[kt * 225 + d];
            #pragma unroll
            for (int i = 0; i < 8; i++) acc[i] += scb[(qbase + i) * 64 + kt] * v;
        }
        __syncthreads();   // all score/Q reads done before overwriting Qs region
        #pragma unroll
        for (int i = 0; i < 8; i++) Os[(qbase + i) * 225 + d] = acc[i];
    }
    __syncthreads();

    // attn_proj + residual accumulate into g_hs
    {
        int qbase = half * 8;
        float acc[8];
        float bb = bp[d];
        #pragma unroll
        for (int i = 0; i < 8; i++) acc[i] = bb;
        for (int c = 0; c < 224; c++) {
            float w = Wp[c * 224 + d];
            #pragma unroll
            for (int i = 0; i < 8; i++) acc[i] += Os[(qbase + i) * 225 + c] * w;
        }
        #pragma unroll
        for (int i = 0; i < 8; i++) {
            int qc = qbase + i;
            int qy = qc >> 2, qx = qc & 3;
            int y2 = wy * 4 + qy, x2 = wx * 4 + qx;
            size_t gid = (((size_t)b * 64 + y2) * 64 + x2) * 224 + d;
            g_hs[gid] += acc[i];
        }
    }
}

// ---------------------------------------------------------------------------
// K4: out = hs + MLP(LN2(hs)); 1024 blocks x 448 threads, 32 tokens/block
// smem: Hs 32x225 | Xln 32x225 | Ha 32x897
// ---------------------------------------------------------------------------
#define HS_N  (32 * 225)   // 7200
#define HA_N  (32 * 897)   // 28704
#define SMEM4 ((2 * HS_N + HA_N) * 4)

__global__ void k_mlp(const float* __restrict__ g2, const float* __restrict__ b2,
                      const float* __restrict__ W1, const float* __restrict__ b1,
                      const float* __restrict__ W2, const float* __restrict__ b2m,
                      float* __restrict__ out) {
    extern __shared__ float sm[];
    float* Hs  = sm;
    float* Xln = sm + HS_N;
    float* Ha  = Xln + HS_N;

    int t0   = blockIdx.x * 32;
    int tid  = threadIdx.x;
    int d    = tid % 224;
    int half = tid / 224;

    for (int e = tid; e < 32 * 224; e += 448) {
        int t = e / 224, c = e - t * 224;
        Hs[t * 225 + c] = g_hs[(size_t)t0 * 224 + e];
    }
    __syncthreads();

    // LN2: warp per token (224 = 7 x 32 lanes)
    int warp = tid >> 5, lane = tid & 31;
    for (int t = warp; t < 32; t += 14) {
        float v[7]; float s = 0.f;
        #pragma unroll
        for (int k = 0; k < 7; k++) { v[k] = Hs[t * 225 + lane + 32 * k]; s += v[k]; }
        #pragma unroll
        for (int o = 16; o; o >>= 1) s += __shfl_xor_sync(~0u, s, o);
        float m = s * (1.f / 224.f);
        float q = 0.f;
        #pragma unroll
        for (int k = 0; k < 7; k++) { v[k] -= m; q += v[k] * v[k]; }
        #pragma unroll
        for (int o = 16; o; o >>= 1) q += __shfl_xor_sync(~0u, q, o);
        float rs = rsqrtf(q * (1.f / 224.f) + 1e-6f);
        #pragma unroll
        for (int k = 0; k < 7; k++) {
            int c = lane + 32 * k;
            Xln[t * 225 + c] = v[k] * rs * g2[c] + b2[c];
        }
    }
    __syncthreads();

    // MLP1 + exact GELU: thread handles hidden dims d+gi*224, tokens half*16..+16
    int tb = half * 16;
    for (int gi = 0; gi < 4; gi++) {
        int h = d + gi * 224;
        float acc[16];
        float bb = b1[h];
        #pragma unroll
        for (int i = 0; i < 16; i++) acc[i] = bb;
        for (int c = 0; c < 224; c++) {
            float w = W1[c * 896 + h];
            #pragma unroll
            for (int i = 0; i < 16; i++) acc[i] += Xln[(tb + i) * 225 + c] * w;
        }
        #pragma unroll
        for (int i = 0; i < 16; i++) {
            float a = acc[i];
            Ha[(tb + i) * 897 + h] = 0.5f * a * (1.f + erff(a * 0.70710678118654752f));
        }
    }
    __syncthreads();

    // MLP2 + residual -> out
    {
        float acc[16];
        float bb = b2m[d];
        #pragma unroll
        for (int i = 0; i < 16; i++) acc[i] = bb;
        for (int h = 0; h < 896; h++) {
            float w = W2[h * 224 + d];
            #pragma unroll
            for (int i = 0; i < 16; i++) acc[i] += Ha[(tb + i) * 897 + h] * w;
        }
        #pragma unroll
        for (int i = 0; i < 16; i++)
            out[(size_t)(t0 + tb + i) * 224 + d] = Hs[(tb + i) * 225 + d] + acc[i];
    }
}

// ---------------------------------------------------------------------------
extern "C" void kernel_launch(void* const* d_in, const int* in_sizes, int n_in,
                              void* d_out, int out_size) {
    const float* hidden   = (const float*)d_in[0];
    const float* ln1_g    = (const float*)d_in[1];
    const float* ln1_b    = (const float*)d_in[2];
    const float* qkv_w    = (const float*)d_in[3];
    const float* qkv_b    = (const float*)d_in[4];
    const float* aproj_w  = (const float*)d_in[5];
    const float* aproj_b  = (const float*)d_in[6];
    const float* rproj_w  = (const float*)d_in[7];
    const float* rproj_b  = (const float*)d_in[8];
    const float* ln2_g    = (const float*)d_in[9];
    const float* ln2_b    = (const float*)d_in[10];
    const float* mlp1_w   = (const float*)d_in[11];
    const float* mlp1_b   = (const float*)d_in[12];
    const float* mlp2_w   = (const float*)d_in[13];
    const float* mlp2_b   = (const float*)d_in[14];
    float* out = (float*)d_out;

    cudaFuncSetAttribute(k_attn, cudaFuncAttributeMaxDynamicSharedMemorySize, SMEM3);
    cudaFuncSetAttribute(k_mlp,  cudaFuncAttributeMaxDynamicSharedMemorySize, SMEM4);

    k_ln1<<<NPIX / 8, 256>>>(hidden, ln1_g, ln1_b);
    k_res<<<NTOK / 8, 224>>>(rproj_w, rproj_b);
    k_attn<<<2048, 448, SMEM3>>>(qkv_w, qkv_b, aproj_w, aproj_b);
    k_mlp<<<1024, 448, SMEM4>>>(ln2_g, ln2_b, mlp1_w, mlp1_b, mlp2_w, mlp2_b, out);
}

// round 2
// speedup vs baseline: 2.1671x; 2.1671x over previous
#include <cuda_runtime.h>
#include <math.h>

#define DIM   112
#define DIMO  224
#define MLPD  896
#define NPIX  (8*128*128)
#define NTOK  (8*64*64)

// Scratch (device globals; no allocation allowed)
__device__ float g_hs_ln[(size_t)NPIX * DIM];   // LN1 output, original layout
__device__ float g_hs[(size_t)NTOK * DIMO];     // residual + attn output ("hs")

// ---------------------------------------------------------------------------
// K1: LayerNorm over DIM=112, warp per pixel
// ---------------------------------------------------------------------------
__global__ void k_ln1(const float* __restrict__ x,
                      const float* __restrict__ g,
                      const float* __restrict__ b) {
    int pix  = blockIdx.x * 8 + (threadIdx.x >> 5);
    int lane = threadIdx.x & 31;
    const float* px = x + (size_t)pix * DIM;
    float v0 = px[lane], v1 = px[lane + 32], v2 = px[lane + 64];
    float v3 = (lane < 16) ? px[lane + 96] : 0.f;
    float s = v0 + v1 + v2 + v3;
    #pragma unroll
    for (int o = 16; o; o >>= 1) s += __shfl_xor_sync(~0u, s, o);
    float m = s * (1.f / 112.f);
    float d0 = v0 - m, d1 = v1 - m, d2 = v2 - m;
    float d3 = (lane < 16) ? v3 - m : 0.f;
    float q = d0*d0 + d1*d1 + d2*d2 + d3*d3;
    #pragma unroll
    for (int o = 16; o; o >>= 1) q += __shfl_xor_sync(~0u, q, o);
    float rs = rsqrtf(q * (1.f / 112.f) + 1e-6f);
    float* po = g_hs_ln + (size_t)pix * DIM;
    po[lane]      = d0 * rs * g[lane]      + b[lane];
    po[lane + 32] = d1 * rs * g[lane + 32] + b[lane + 32];
    po[lane + 64] = d2 * rs * g[lane + 64] + b[lane + 64];
    if (lane < 16) po[lane + 96] = d3 * rs * g[lane + 96] + b[lane + 96];
}

// ---------------------------------------------------------------------------
// K2: residual = maxpool2(hs_ln @ res_proj_w + b) -> g_hs
// Block: 8 out tokens, 448 threads = 8 tok x 56 dgroups; tile 4 cells x 4 dims
// Xrt[c][p'] transposed, p' = j*4 + dy*2 + dx (pool-cell-major)
// ---------------------------------------------------------------------------
__global__ void __launch_bounds__(448) k_res(const float* __restrict__ W,
                                             const float* __restrict__ bias) {
    __shared__ float Xrt[112 * 36];
    int t0  = blockIdx.x * 8;
    int b   = t0 >> 12;
    int rem = t0 & 4095;
    int y2  = rem >> 6;
    int x2b = rem & 63;
    int tid = threadIdx.x;

    // stage transposed: each e is one (pixel-cell, c4) float4
    for (int e = tid; e < 32 * 28; e += 448) {
        int p = e / 28, c4 = (e - p * 28) * 4;
        int j = p >> 2, cell = p & 3;
        int dy = cell >> 1, dx = cell & 1;
        int y = 2 * y2 + dy, x = 2 * (x2b + j) + dx;
        float4 v = *(const float4*)&g_hs_ln[(((size_t)b * 128 + y) * 128 + x) * 112 + c4];
        Xrt[(c4 + 0) * 36 + p] = v.x;
        Xrt[(c4 + 1) * 36 + p] = v.y;
        Xrt[(c4 + 2) * 36 + p] = v.z;
        Xrt[(c4 + 3) * 36 + p] = v.w;
    }
    __syncthreads();

    int j  = tid / 56;          // out token 0..7
    int d0 = (tid % 56) * 4;
    float acc[4][4];
    #pragma unroll
    for (int a = 0; a < 4; a++)
        #pragma unroll
        for (int c = 0; c < 4; c++) acc[a][c] = 0.f;

    for (int c = 0; c < 112; c++) {
        float4 xv = *(const float4*)&Xrt[c * 36 + j * 4];
        float4 wv = *(const float4*)&W[c * 224 + d0];
        float xs[4] = {xv.x, xv.y, xv.z, xv.w};
        float ws[4] = {wv.x, wv.y, wv.z, wv.w};
        #pragma unroll
        for (int a = 0; a < 4; a++)
            #pragma unroll
            for (int cc = 0; cc < 4; cc++) acc[a][cc] += xs[a] * ws[cc];
    }
    float4 bb = *(const float4*)&bias[d0];
    float4 r;
    r.x = fmaxf(fmaxf(acc[0][0], acc[1][0]), fmaxf(acc[2][0], acc[3][0])) + bb.x;
    r.y = fmaxf(fmaxf(acc[0][1], acc[1][1]), fmaxf(acc[2][1], acc[3][1])) + bb.y;
    r.z = fmaxf(fmaxf(acc[0][2], acc[1][2]), fmaxf(acc[2][2], acc[3][2])) + bb.z;
    r.w = fmaxf(fmaxf(acc[0][3], acc[1][3]), fmaxf(acc[2][3], acc[3][3])) + bb.w;
    *(float4*)&g_hs[(size_t)(t0 + j) * 224 + d0] = r;
}

// ---------------------------------------------------------------------------
// K3: per-window attention. 2048 blocks x 448 threads.
// smem: Xst[112][68] | Kt[224][68] | Vrow[64][228] | QrawT[224][68] | Qt[224][20]
// P(64x64) aliases Xst; OT(224x20) aliases QrawT
// ---------------------------------------------------------------------------
#define XST_N  (112 * 68)     // 7616
#define KT_N   (224 * 68)     // 15232
#define VR_N   (64 * 228)     // 14592
#define QT_N   (224 * 20)     // 4480
#define SMEM3  ((XST_N + KT_N + VR_N + KT_N + QT_N) * 4)

__global__ void __launch_bounds__(448) k_attn(
        const float* __restrict__ Wqkv, const float* __restrict__ bqkv,
        const float* __restrict__ Wp,   const float* __restrict__ bp) {
    extern __shared__ float sm[];
    float* Xst   = sm;                 // [c][t] stride 68
    float* Kt    = Xst + XST_N;        // [d][t] stride 68
    float* Vrow  = Kt + KT_N;          // [t][d] stride 228
    float* QrawT = Vrow + VR_N;        // [d][t] stride 68
    float* Qt    = QrawT + KT_N;       // [d][q] stride 20
    float* P     = Xst;                // 64x64 scores (alias)
    float* OT    = QrawT;              // [c][q] stride 20 (alias)

    int wi = blockIdx.x;
    int b  = wi >> 8;
    int r  = wi & 255;
    int wy = r >> 4, wx = r & 15;
    int tid = threadIdx.x;

    // stage window transposed: 64 tok x 112 -> Xst[c][t]
    for (int e = tid; e < 64 * 28; e += 448) {
        int t = e / 28, c4 = (e - t * 28) * 4;
        int ty = t >> 3, tx = t & 7;
        int y = wy * 8 + ty, x = wx * 8 + tx;
        float4 v = *(const float4*)&g_hs_ln[(((size_t)b * 128 + y) * 128 + x) * 112 + c4];
        Xst[(c4 + 0) * 68 + t] = v.x;
        Xst[(c4 + 1) * 68 + t] = v.y;
        Xst[(c4 + 2) * 68 + t] = v.z;
        Xst[(c4 + 3) * 68 + t] = v.w;
    }
    __syncthreads();

    // QKV GEMMs: 64 tok x 224 dims each; thread tile 8 tok x 4 dims
    int tg = tid / 56;          // token group 0..7
    int d0 = (tid % 56) * 4;
    int tt0 = tg * 8;

    // ---- K (offset 224) ----
    {
        float acc[8][4];
        float4 bb = *(const float4*)&bqkv[224 + d0];
        #pragma unroll
        for (int i = 0; i < 8; i++) { acc[i][0]=bb.x; acc[i][1]=bb.y; acc[i][2]=bb.z; acc[i][3]=bb.w; }
        for (int c = 0; c < 112; c++) {
            float4 x0 = *(const float4*)&Xst[c * 68 + tt0];
            float4 x1 = *(const float4*)&Xst[c * 68 + tt0 + 4];
            float4 wv = *(const float4*)&Wqkv[c * 672 + 224 + d0];
            float xs[8] = {x0.x,x0.y,x0.z,x0.w,x1.x,x1.y,x1.z,x1.w};
            float ws[4] = {wv.x,wv.y,wv.z,wv.w};
            #pragma unroll
            for (int i = 0; i < 8; i++)
                #pragma unroll
                for (int jj = 0; jj < 4; jj++) acc[i][jj] += xs[i] * ws[jj];
        }
        #pragma unroll
        for (int jj = 0; jj < 4; jj++) {
            float4 v0 = make_float4(acc[0][jj], acc[1][jj], acc[2][jj], acc[3][jj]);
            float4 v1 = make_float4(acc[4][jj], acc[5][jj], acc[6][jj], acc[7][jj]);
            *(float4*)&Kt[(d0 + jj) * 68 + tt0]     = v0;
            *(float4*)&Kt[(d0 + jj) * 68 + tt0 + 4] = v1;
        }
    }
    // ---- V (offset 448) ----
    {
        float acc[8][4];
        float4 bb = *(const float4*)&bqkv[448 + d0];
        #pragma unroll
        for (int i = 0; i < 8; i++) { acc[i][0]=bb.x; acc[i][1]=bb.y; acc[i][2]=bb.z; acc[i][3]=bb.w; }
        for (int c = 0; c < 112; c++) {
            float4 x0 = *(const float4*)&Xst[c * 68 + tt0];
            float4 x1 = *(const float4*)&Xst[c * 68 + tt0 + 4];
            float4 wv = *(const float4*)&Wqkv[c * 672 + 448 + d0];
            float xs[8] = {x0.x,x0.y,x0.z,x0.w,x1.x,x1.y,x1.z,x1.w};
            float ws[4] = {wv.x,wv.y,wv.z,wv.w};
            #pragma unroll
            for (int i = 0; i < 8; i++)
                #pragma unroll
                for (int jj = 0; jj < 4; jj++) acc[i][jj] += xs[i] * ws[jj];
        }
        #pragma unroll
        for (int i = 0; i < 8; i++)
            *(float4*)&Vrow[(tt0 + i) * 228 + d0] =
                make_float4(acc[i][0], acc[i][1], acc[i][2], acc[i][3]);
    }
    // ---- Q raw (offset 0) ----
    {
        float acc[8][4];
        float4 bb = *(const float4*)&bqkv[d0];
        #pragma unroll
        for (int i = 0; i < 8; i++) { acc[i][0]=bb.x; acc[i][1]=bb.y; acc[i][2]=bb.z; acc[i][3]=bb.w; }
        for (int c = 0; c < 112; c++) {
            float4 x0 = *(const float4*)&Xst[c * 68 + tt0];
            float4 x1 = *(const float4*)&Xst[c * 68 + tt0 + 4];
            float4 wv = *(const float4*)&Wqkv[c * 672 + d0];
            float xs[8] = {x0.x,x0.y,x0.z,x0.w,x1.x,x1.y,x1.z,x1.w};
            float ws[4] = {wv.x,wv.y,wv.z,wv.w};
            #pragma unroll
            for (int i = 0; i < 8; i++)
                #pragma unroll
                for (int jj = 0; jj < 4; jj++) acc[i][jj] += xs[i] * ws[jj];
        }
        #pragma unroll
        for (int jj = 0; jj < 4; jj++) {
            float4 v0 = make_float4(acc[0][jj], acc[1][jj], acc[2][jj], acc[3][jj]);
            float4 v1 = make_float4(acc[4][jj], acc[5][jj], acc[6][jj], acc[7][jj]);
            *(float4*)&QrawT[(d0 + jj) * 68 + tt0]     = v0;
            *(float4*)&QrawT[(d0 + jj) * 68 + tt0 + 4] = v1;
        }
    }
    __syncthreads();

    // Q pooling: Qt[d][q] = max over 2x2 token cell
    for (int e = tid; e < 224 * 16; e += 448) {
        int d = e >> 4, q = e & 15;
        int qy = q >> 2, qx = q & 3;
        const float* qr = QrawT + d * 68;
        float m = fmaxf(fmaxf(qr[(2*qy)*8 + 2*qx],     qr[(2*qy)*8 + 2*qx + 1]),
                        fmaxf(qr[(2*qy+1)*8 + 2*qx],   qr[(2*qy+1)*8 + 2*qx + 1]));
        Qt[d * 20 + q] = m;
    }
    __syncthreads();

    // scores: 256 threads, tile 4q x 4k per (head)
    const float scale = 0.13363062095621219f;   // 56^-0.5
    if (tid < 256) {
        int h  = tid >> 6;
        int q0 = ((tid >> 4) & 3) * 4;
        int k0 = (tid & 15) * 4;
        float acc[4][4];
        #pragma unroll
        for (int a = 0; a < 4; a++)
            #pragma unroll
            for (int c = 0; c < 4; c++) acc[a][c] = 0.f;
        for (int hd = 0; hd < 56; hd++) {
            int d = h * 56 + hd;
            float4 qv = *(const float4*)&Qt[d * 20 + q0];
            float4 kv = *(const float4*)&Kt[d * 68 + k0];
            float qs[4] = {qv.x,qv.y,qv.z,qv.w};
            float ks[4] = {kv.x,kv.y,kv.z,kv.w};
            #pragma unroll
            for (int a = 0; a < 4; a++)
                #pragma unroll
                for (int c = 0; c < 4; c++) acc[a][c] += qs[a] * ks[c];
        }
        #pragma unroll
        for (int a = 0; a < 4; a++)
            *(float4*)&P[(h * 16 + q0 + a) * 64 + k0] =
                make_float4(acc[a][0]*scale, acc[a][1]*scale, acc[a][2]*scale, acc[a][3]*scale);
    }
    __syncthreads();

    // softmax over 64 rows of 64 (warp per row)
    int warp = tid >> 5, lane = tid & 31;
    for (int rr = warp; rr < 64; rr += 14) {
        float* row = P + rr * 64;
        float a = row[lane], c2 = row[lane + 32];
        float mx = fmaxf(a, c2);
        #pragma unroll
        for (int o = 16; o; o >>= 1) mx = fmaxf(mx, __shfl_xor_sync(~0u, mx, o));
        a = __expf(a - mx); c2 = __expf(c2 - mx);
        float s = a + c2;
        #pragma unroll
        for (int o = 16; o; o >>= 1) s += __shfl_xor_sync(~0u, s, o);
        float inv = 1.f / s;
        row[lane] = a * inv; row[lane + 32] = c2 * inv;
    }
    __syncthreads();

    // PV: 224 threads, tile 4q x 4d -> OT[d][q] (aliases QrawT, dead)
    if (tid < 224) {
        int dg = tid % 56, qg = tid / 56;
        int dd0 = dg * 4, q0 = qg * 4;
        int h = dd0 / 56;
        float acc[4][4];
        #pragma unroll
        for (int a = 0; a < 4; a++)
            #pragma unroll
            for (int c = 0; c < 4; c++) acc[a][c] = 0.f;
        for (int k = 0; k < 64; k++) {
            float4 vv = *(const float4*)&Vrow[k * 228 + dd0];
            float vs[4] = {vv.x,vv.y,vv.z,vv.w};
            float pq[4];
            #pragma unroll
            for (int a = 0; a < 4; a++) pq[a] = P[(h * 16 + q0 + a) * 64 + k];
            #pragma unroll
            for (int a = 0; a < 4; a++)
                #pragma unroll
                for (int c = 0; c < 4; c++) acc[a][c] += pq[a] * vs[c];
        }
        #pragma unroll
        for (int c = 0; c < 4; c++)
            *(float4*)&OT[(dd0 + c) * 20 + q0] =
                make_float4(acc[0][c], acc[1][c], acc[2][c], acc[3][c]);
    }
    __syncthreads();

    // attn_proj + residual accumulate: 224 threads, tile 4q x 4d
    if (tid < 224) {
        int dg = tid % 56, qg = tid / 56;
        int dd0 = dg * 4, q0 = qg * 4;
        float acc[4][4];
        float4 bb = *(const float4*)&bp[dd0];
        #pragma unroll
        for (int a = 0; a < 4; a++) { acc[a][0]=bb.x; acc[a][1]=bb.y; acc[a][2]=bb.z; acc[a][3]=bb.w; }
        for (int c = 0; c < 224; c++) {
            float4 ov = *(const float4*)&OT[c * 20 + q0];
            float4 wv = *(const float4*)&Wp[c * 224 + dd0];
            float os[4] = {ov.x,ov.y,ov.z,ov.w};
            float ws[4] = {wv.x,wv.y,wv.z,wv.w};
            #pragma unroll
            for (int a = 0; a < 4; a++)
                #pragma unroll
                for (int cc = 0; cc < 4; cc++) acc[a][cc] += os[a] * ws[cc];
        }
        #pragma unroll
        for (int a = 0; a < 4; a++) {
            int q = q0 + a;
            int qy = q >> 2, qx = q & 3;
            int y2 = wy * 4 + qy, x2 = wx * 4 + qx;
            size_t gid = (((size_t)b * 64 + y2) * 64 + x2) * 224 + dd0;
            float4 g = *(float4*)&g_hs[gid];
            g.x += acc[a][0]; g.y += acc[a][1]; g.z += acc[a][2]; g.w += acc[a][3];
            *(float4*)&g_hs[gid] = g;
        }
    }
}

// ---------------------------------------------------------------------------
// K4: out = hs + MLP(LN2(hs)); 1024 blocks x 448 threads, 32 tokens/block
// smem: Hs[32][228] | XlnT[224][36] | HaT[896][36]
// ---------------------------------------------------------------------------
#define HS_N   (32 * 228)    // 7296
#define XLN_N  (224 * 36)    // 8064
#define HAT_N  (896 * 36)    // 32256
#define SMEM4  ((HS_N + XLN_N + HAT_N) * 4)

__global__ void __launch_bounds__(448) k_mlp(
        const float* __restrict__ g2, const float* __restrict__ b2,
        const float* __restrict__ W1, const float* __restrict__ b1,
        const float* __restrict__ W2, const float* __restrict__ b2m,
        float* __restrict__ out) {
    extern __shared__ float sm[];
    float* Hs   = sm;                  // [t][d] stride 228
    float* XlnT = sm + HS_N;           // [c][t] stride 36
    float* HaT  = XlnT + XLN_N;        // [h][t] stride 36

    int t0  = blockIdx.x * 32;
    int tid = threadIdx.x;

    // stage hs rows (vectorized copy)
    for (int e = tid; e < 32 * 56; e += 448) {
        int t = e / 56, c4 = (e - t * 56) * 4;
        *(float4*)&Hs[t * 228 + c4] =
            *(const float4*)&g_hs[(size_t)(t0 + t) * 224 + c4];
    }
    __syncthreads();

    // LN2 (warp per token) -> XlnT transposed
    int warp = tid >> 5, lane = tid & 31;
    for (int t = warp; t < 32; t += 14) {
        float v[7]; float s = 0.f;
        #pragma unroll
        for (int k = 0; k < 7; k++) { v[k] = Hs[t * 228 + lane + 32 * k]; s += v[k]; }
        #pragma unroll
        for (int o = 16; o; o >>= 1) s += __shfl_xor_sync(~0u, s, o);
        float m = s * (1.f / 224.f);
        float q = 0.f;
        #pragma unroll
        for (int k = 0; k < 7; k++) { v[k] -= m; q += v[k] * v[k]; }
        #pragma unroll
        for (int o = 16; o; o >>= 1) q += __shfl_xor_sync(~0u, q, o);
        float rs = rsqrtf(q * (1.f / 224.f) + 1e-6f);
        #pragma unroll
        for (int k = 0; k < 7; k++) {
            int c = lane + 32 * k;
            XlnT[c * 36 + t] = v[k] * rs * g2[c] + b2[c];
        }
    }
    __syncthreads();

    // MLP1 + GELU: thread tile 8 tok x 8 hid (4 tg x 112 hg)
    {
        int tg = tid / 112;
        int h0 = (tid % 112) * 8;
        int tb = tg * 8;
        float acc[8][8];
        #pragma unroll
        for (int jj = 0; jj < 8; jj++) {
            float bb = b1[h0 + jj];
            #pragma unroll
            for (int i = 0; i < 8; i++) acc[i][jj] = bb;
        }
        for (int c = 0; c < 224; c++) {
            float4 x0 = *(const float4*)&XlnT[c * 36 + tb];
            float4 x1 = *(const float4*)&XlnT[c * 36 + tb + 4];
            float4 w0 = *(const float4*)&W1[c * 896 + h0];
            float4 w1 = *(const float4*)&W1[c * 896 + h0 + 4];
            float xs[8] = {x0.x,x0.y,x0.z,x0.w,x1.x,x1.y,x1.z,x1.w};
            float ws[8] = {w0.x,w0.y,w0.z,w0.w,w1.x,w1.y,w1.z,w1.w};
            #pragma unroll
            for (int i = 0; i < 8; i++)
                #pragma unroll
                for (int jj = 0; jj < 8; jj++) acc[i][jj] += xs[i] * ws[jj];
        }
        #pragma unroll
        for (int jj = 0; jj < 8; jj++) {
            float g[8];
            #pragma unroll
            for (int i = 0; i < 8; i++) {
                float a = acc[i][jj];
                g[i] = 0.5f * a * (1.f + erff(a * 0.70710678118654752f));
            }
            *(float4*)&HaT[(h0 + jj) * 36 + tb]     = make_float4(g[0],g[1],g[2],g[3]);
            *(float4*)&HaT[(h0 + jj) * 36 + tb + 4] = make_float4(g[4],g[5],g[6],g[7]);
        }
    }
    __syncthreads();

    // MLP2 + residual: thread tile 4 tok x 4 d (8 tg x 56 dg)
    {
        int tg = tid / 56;
        int d0 = (tid % 56) * 4;
        int tb = tg * 4;
        float acc[4][4];
        float4 bb = *(const float4*)&b2m[d0];
        #pragma unroll
        for (int a = 0; a < 4; a++) { acc[a][0]=bb.x; acc[a][1]=bb.y; acc[a][2]=bb.z; acc[a][3]=bb.w; }
        for (int h = 0; h < 896; h++) {
            float4 hv = *(const float4*)&HaT[h * 36 + tb];
            float4 wv = *(const float4*)&W2[h * 224 + d0];
            float hs_[4] = {hv.x,hv.y,hv.z,hv.w};
            float ws[4]  = {wv.x,wv.y,wv.z,wv.w};
            #pragma unroll
            for (int a = 0; a < 4; a++)
                #pragma unroll
                for (int c = 0; c < 4; c++) acc[a][c] += hs_[a] * ws[c];
        }
        #pragma unroll
        for (int a = 0; a < 4; a++) {
            float4 hres = *(const float4*)&Hs[(tb + a) * 228 + d0];
            *(float4*)&out[(size_t)(t0 + tb + a) * 224 + d0] =
                make_float4(hres.x + acc[a][0], hres.y + acc[a][1],
                            hres.z + acc[a][2], hres.w + acc[a][3]);
        }
    }
}

// ---------------------------------------------------------------------------
extern "C" void kernel_launch(void* const* d_in, const int* in_sizes, int n_in,
                              void* d_out, int out_size) {
    const float* hidden   = (const float*)d_in[0];
    const float* ln1_g    = (const float*)d_in[1];
    const float* ln1_b    = (const float*)d_in[2];
    const float* qkv_w    = (const float*)d_in[3];
    const float* qkv_b    = (const float*)d_in[4];
    const float* aproj_w  = (const float*)d_in[5];
    const float* aproj_b  = (const float*)d_in[6];
    const float* rproj_w  = (const float*)d_in[7];
    const float* rproj_b  = (const float*)d_in[8];
    const float* ln2_g    = (const float*)d_in[9];
    const float* ln2_b    = (const float*)d_in[10];
    const float* mlp1_w   = (const float*)d_in[11];
    const float* mlp1_b   = (const float*)d_in[12];
    const float* mlp2_w   = (const float*)d_in[13];
    const float* mlp2_b   = (const float*)d_in[14];
    float* out = (float*)d_out;

    cudaFuncSetAttribute(k_attn, cudaFuncAttributeMaxDynamicSharedMemorySize, SMEM3);
    cudaFuncSetAttribute(k_mlp,  cudaFuncAttributeMaxDynamicSharedMemorySize, SMEM4);

    k_ln1<<<NPIX / 8, 256>>>(hidden, ln1_g, ln1_b);
    k_res<<<NTOK / 8, 448>>>(rproj_w, rproj_b);
    k_attn<<<2048, 448, SMEM3>>>(qkv_w, qkv_b, aproj_w, aproj_b);
    k_mlp<<<1024, 448, SMEM4>>>(ln2_g, ln2_b, mlp1_w, mlp1_b, mlp2_w, mlp2_b, out);
}

// round 3
// speedup vs baseline: 2.6069x; 1.2029x over previous
#include <cuda_runtime.h>
#include <math.h>

#define DIM   112
#define DIMO  224
#define MLPD  896
#define NPIX  (8*128*128)
#define NTOK  (8*64*64)

// Scratch (device globals; no allocation allowed)
__device__ float g_hs_ln[(size_t)NPIX * DIM];   // LN1 output, original layout
__device__ float g_hs[(size_t)NTOK * DIMO];     // residual + attn output ("hs")
__device__ float g_w1t[224 * 896];              // tf32-rounded mlp1_w
__device__ float g_w2t[896 * 224];              // tf32-rounded mlp2_w

__device__ __forceinline__ unsigned f2tf32(float x) {
    unsigned r;
    asm("cvt.rna.tf32.f32 %0, %1;" : "=r"(r) : "f"(x));
    return r;
}

__device__ __forceinline__ void mma_tf32(float* c,
        unsigned a0, unsigned a1, unsigned a2, unsigned a3,
        unsigned b0, unsigned b1) {
    asm("mma.sync.aligned.m16n8k8.row.col.f32.tf32.tf32.f32 "
        "{%0,%1,%2,%3}, {%4,%5,%6,%7}, {%8,%9}, {%0,%1,%2,%3};"
        : "+f"(c[0]), "+f"(c[1]), "+f"(c[2]), "+f"(c[3])
        : "r"(a0), "r"(a1), "r"(a2), "r"(a3), "r"(b0), "r"(b1));
}

// ---------------------------------------------------------------------------
// K0: round MLP weights to tf32 once per launch (both arrays are 200704 elems)
// ---------------------------------------------------------------------------
__global__ void k_prep(const float* __restrict__ W1, const float* __restrict__ W2) {
    int i = blockIdx.x * 1024 + threadIdx.x;
    if (i < 224 * 896) {
        g_w1t[i] = __uint_as_float(f2tf32(W1[i]));
        g_w2t[i] = __uint_as_float(f2tf32(W2[i]));
    }
}

// ---------------------------------------------------------------------------
// K1: LayerNorm over DIM=112, warp per pixel
// ---------------------------------------------------------------------------
__global__ void k_ln1(const float* __restrict__ x,
                      const float* __restrict__ g,
                      const float* __restrict__ b) {
    int pix  = blockIdx.x * 8 + (threadIdx.x >> 5);
    int lane = threadIdx.x & 31;
    const float* px = x + (size_t)pix * DIM;
    float v0 = px[lane], v1 = px[lane + 32], v2 = px[lane + 64];
    float v3 = (lane < 16) ? px[lane + 96] : 0.f;
    float s = v0 + v1 + v2 + v3;
    #pragma unroll
    for (int o = 16; o; o >>= 1) s += __shfl_xor_sync(~0u, s, o);
    float m = s * (1.f / 112.f);
    float d0 = v0 - m, d1 = v1 - m, d2 = v2 - m;
    float d3 = (lane < 16) ? v3 - m : 0.f;
    float q = d0*d0 + d1*d1 + d2*d2 + d3*d3;
    #pragma unroll
    for (int o = 16; o; o >>= 1) q += __shfl_xor_sync(~0u, q, o);
    float rs = rsqrtf(q * (1.f / 112.f) + 1e-6f);
    float* po = g_hs_ln + (size_t)pix * DIM;
    po[lane]      = d0 * rs * g[lane]      + b[lane];
    po[lane + 32] = d1 * rs * g[lane + 32] + b[lane + 32];
    po[lane + 64] = d2 * rs * g[lane + 64] + b[lane + 64];
    if (lane < 16) po[lane + 96] = d3 * rs * g[lane + 96] + b[lane + 96];
}

// ---------------------------------------------------------------------------
// K2: residual = maxpool2(hs_ln @ res_proj_w + b) -> g_hs
// ---------------------------------------------------------------------------
__global__ void __launch_bounds__(448) k_res(const float* __restrict__ W,
                                             const float* __restrict__ bias) {
    __shared__ float Xrt[112 * 36];
    int t0  = blockIdx.x * 8;
    int b   = t0 >> 12;
    int rem = t0 & 4095;
    int y2  = rem >> 6;
    int x2b = rem & 63;
    int tid = threadIdx.x;

    for (int e = tid; e < 32 * 28; e += 448) {
        int p = e / 28, c4 = (e - p * 28) * 4;
        int j = p >> 2, cell = p & 3;
        int dy = cell >> 1, dx = cell & 1;
        int y = 2 * y2 + dy, x = 2 * (x2b + j) + dx;
        float4 v = *(const float4*)&g_hs_ln[(((size_t)b * 128 + y) * 128 + x) * 112 + c4];
        Xrt[(c4 + 0) * 36 + p] = v.x;
        Xrt[(c4 + 1) * 36 + p] = v.y;
        Xrt[(c4 + 2) * 36 + p] = v.z;
        Xrt[(c4 + 3) * 36 + p] = v.w;
    }
    __syncthreads();

    int j  = tid / 56;
    int d0 = (tid % 56) * 4;
    float acc[4][4];
    #pragma unroll
    for (int a = 0; a < 4; a++)
        #pragma unroll
        for (int c = 0; c < 4; c++) acc[a][c] = 0.f;

    for (int c = 0; c < 112; c++) {
        float4 xv = *(const float4*)&Xrt[c * 36 + j * 4];
        float4 wv = *(const float4*)&W[c * 224 + d0];
        float xs[4] = {xv.x, xv.y, xv.z, xv.w};
        float ws[4] = {wv.x, wv.y, wv.z, wv.w};
        #pragma unroll
        for (int a = 0; a < 4; a++)
            #pragma unroll
            for (int cc = 0; cc < 4; cc++) acc[a][cc] += xs[a] * ws[cc];
    }
    float4 bb = *(const float4*)&bias[d0];
    float4 r;
    r.x = fmaxf(fmaxf(acc[0][0], acc[1][0]), fmaxf(acc[2][0], acc[3][0])) + bb.x;
    r.y = fmaxf(fmaxf(acc[0][1], acc[1][1]), fmaxf(acc[2][1], acc[3][1])) + bb.y;
    r.z = fmaxf(fmaxf(acc[0][2], acc[1][2]), fmaxf(acc[2][2], acc[3][2])) + bb.z;
    r.w = fmaxf(fmaxf(acc[0][3], acc[1][3]), fmaxf(acc[2][3], acc[3][3])) + bb.w;
    *(float4*)&g_hs[(size_t)(t0 + j) * 224 + d0] = r;
}

// ---------------------------------------------------------------------------
// K3: per-window attention (fp32, unchanged from round 2)
// ---------------------------------------------------------------------------
#define XST_N  (112 * 68)
#define KT_N   (224 * 68)
#define VR_N   (64 * 228)
#define QT_N   (224 * 20)
#define SMEM3  ((XST_N + KT_N + VR_N + KT_N + QT_N) * 4)

__global__ void __launch_bounds__(448) k_attn(
        const float* __restrict__ Wqkv, const float* __restrict__ bqkv,
        const float* __restrict__ Wp,   const float* __restrict__ bp) {
    extern __shared__ float sm[];
    float* Xst   = sm;
    float* Kt    = Xst + XST_N;
    float* Vrow  = Kt + KT_N;
    float* QrawT = Vrow + VR_N;
    float* Qt    = QrawT + KT_N;
    float* P     = Xst;
    float* OT    = QrawT;

    int wi = blockIdx.x;
    int b  = wi >> 8;
    int r  = wi & 255;
    int wy = r >> 4, wx = r & 15;
    int tid = threadIdx.x;

    for (int e = tid; e < 64 * 28; e += 448) {
        int t = e / 28, c4 = (e - t * 28) * 4;
        int ty = t >> 3, tx = t & 7;
        int y = wy * 8 + ty, x = wx * 8 + tx;
        float4 v = *(const float4*)&g_hs_ln[(((size_t)b * 128 + y) * 128 + x) * 112 + c4];
        Xst[(c4 + 0) * 68 + t] = v.x;
        Xst[(c4 + 1) * 68 + t] = v.y;
        Xst[(c4 + 2) * 68 + t] = v.z;
        Xst[(c4 + 3) * 68 + t] = v.w;
    }
    __syncthreads();

    int tg = tid / 56;
    int d0 = (tid % 56) * 4;
    int tt0 = tg * 8;

    {
        float acc[8][4];
        float4 bb = *(const float4*)&bqkv[224 + d0];
        #pragma unroll
        for (int i = 0; i < 8; i++) { acc[i][0]=bb.x; acc[i][1]=bb.y; acc[i][2]=bb.z; acc[i][3]=bb.w; }
        for (int c = 0; c < 112; c++) {
            float4 x0 = *(const float4*)&Xst[c * 68 + tt0];
            float4 x1 = *(const float4*)&Xst[c * 68 + tt0 + 4];
            float4 wv = *(const float4*)&Wqkv[c * 672 + 224 + d0];
            float xs[8] = {x0.x,x0.y,x0.z,x0.w,x1.x,x1.y,x1.z,x1.w};
            float ws[4] = {wv.x,wv.y,wv.z,wv.w};
            #pragma unroll
            for (int i = 0; i < 8; i++)
                #pragma unroll
                for (int jj = 0; jj < 4; jj++) acc[i][jj] += xs[i] * ws[jj];
        }
        #pragma unroll
        for (int jj = 0; jj < 4; jj++) {
            float4 v0 = make_float4(acc[0][jj], acc[1][jj], acc[2][jj], acc[3][jj]);
            float4 v1 = make_float4(acc[4][jj], acc[5][jj], acc[6][jj], acc[7][jj]);
            *(float4*)&Kt[(d0 + jj) * 68 + tt0]     = v0;
            *(float4*)&Kt[(d0 + jj) * 68 + tt0 + 4] = v1;
        }
    }
    {
        float acc[8][4];
        float4 bb = *(const float4*)&bqkv[448 + d0];
        #pragma unroll
        for (int i = 0; i < 8; i++) { acc[i][0]=bb.x; acc[i][1]=bb.y; acc[i][2]=bb.z; acc[i][3]=bb.w; }
        for (int c = 0; c < 112; c++) {
            float4 x0 = *(const float4*)&Xst[c * 68 + tt0];
            float4 x1 = *(const float4*)&Xst[c * 68 + tt0 + 4];
            float4 wv = *(const float4*)&Wqkv[c * 672 + 448 + d0];
            float xs[8] = {x0.x,x0.y,x0.z,x0.w,x1.x,x1.y,x1.z,x1.w};
            float ws[4] = {wv.x,wv.y,wv.z,wv.w};
            #pragma unroll
            for (int i = 0; i < 8; i++)
                #pragma unroll
                for (int jj = 0; jj < 4; jj++) acc[i][jj] += xs[i] * ws[jj];
        }
        #pragma unroll
        for (int i = 0; i < 8; i++)
            *(float4*)&Vrow[(tt0 + i) * 228 + d0] =
                make_float4(acc[i][0], acc[i][1], acc[i][2], acc[i][3]);
    }
    {
        float acc[8][4];
        float4 bb = *(const float4*)&bqkv[d0];
        #pragma unroll
        for (int i = 0; i < 8; i++) { acc[i][0]=bb.x; acc[i][1]=bb.y; acc[i][2]=bb.z; acc[i][3]=bb.w; }
        for (int c = 0; c < 112; c++) {
            float4 x0 = *(const float4*)&Xst[c * 68 + tt0];
            float4 x1 = *(const float4*)&Xst[c * 68 + tt0 + 4];
            float4 wv = *(const float4*)&Wqkv[c * 672 + d0];
            float xs[8] = {x0.x,x0.y,x0.z,x0.w,x1.x,x1.y,x1.z,x1.w};
            float ws[4] = {wv.x,wv.y,wv.z,wv.w};
            #pragma unroll
            for (int i = 0; i < 8; i++)
                #pragma unroll
                for (int jj = 0; jj < 4; jj++) acc[i][jj] += xs[i] * ws[jj];
        }
        #pragma unroll
        for (int jj = 0; jj < 4; jj++) {
            float4 v0 = make_float4(acc[0][jj], acc[1][jj], acc[2][jj], acc[3][jj]);
            float4 v1 = make_float4(acc[4][jj], acc[5][jj], acc[6][jj], acc[7][jj]);
            *(float4*)&QrawT[(d0 + jj) * 68 + tt0]     = v0;
            *(float4*)&QrawT[(d0 + jj) * 68 + tt0 + 4] = v1;
        }
    }
    __syncthreads();

    for (int e = tid; e < 224 * 16; e += 448) {
        int d = e >> 4, q = e & 15;
        int qy = q >> 2, qx = q & 3;
        const float* qr = QrawT + d * 68;
        float m = fmaxf(fmaxf(qr[(2*qy)*8 + 2*qx],     qr[(2*qy)*8 + 2*qx + 1]),
                        fmaxf(qr[(2*qy+1)*8 + 2*qx],   qr[(2*qy+1)*8 + 2*qx + 1]));
        Qt[d * 20 + q] = m;
    }
    __syncthreads();

    const float scale = 0.13363062095621219f;
    if (tid < 256) {
        int h  = tid >> 6;
        int q0 = ((tid >> 4) & 3) * 4;
        int k0 = (tid & 15) * 4;
        float acc[4][4];
        #pragma unroll
        for (int a = 0; a < 4; a++)
            #pragma unroll
            for (int c = 0; c < 4; c++) acc[a][c] = 0.f;
        for (int hd = 0; hd < 56; hd++) {
            int d = h * 56 + hd;
            float4 qv = *(const float4*)&Qt[d * 20 + q0];
            float4 kv = *(const float4*)&Kt[d * 68 + k0];
            float qs[4] = {qv.x,qv.y,qv.z,qv.w};
            float ks[4] = {kv.x,kv.y,kv.z,kv.w};
            #pragma unroll
            for (int a = 0; a < 4; a++)
                #pragma unroll
                for (int c = 0; c < 4; c++) acc[a][c] += qs[a] * ks[c];
        }
        #pragma unroll
        for (int a = 0; a < 4; a++)
            *(float4*)&P[(h * 16 + q0 + a) * 64 + k0] =
                make_float4(acc[a][0]*scale, acc[a][1]*scale, acc[a][2]*scale, acc[a][3]*scale);
    }
    __syncthreads();

    int warp = tid >> 5, lane = tid & 31;
    for (int rr = warp; rr < 64; rr += 14) {
        float* row = P + rr * 64;
        float a = row[lane], c2 = row[lane + 32];
        float mx = fmaxf(a, c2);
        #pragma unroll
        for (int o = 16; o; o >>= 1) mx = fmaxf(mx, __shfl_xor_sync(~0u, mx, o));
        a = __expf(a - mx); c2 = __expf(c2 - mx);
        float s = a + c2;
        #pragma unroll
        for (int o = 16; o; o >>= 1) s += __shfl_xor_sync(~0u, s, o);
        float inv = 1.f / s;
        row[lane] = a * inv; row[lane + 32] = c2 * inv;
    }
    __syncthreads();

    if (tid < 224) {
        int dg = tid % 56, qg = tid / 56;
        int dd0 = dg * 4, q0 = qg * 4;
        int h = dd0 / 56;
        float acc[4][4];
        #pragma unroll
        for (int a = 0; a < 4; a++)
            #pragma unroll
            for (int c = 0; c < 4; c++) acc[a][c] = 0.f;
        for (int k = 0; k < 64; k++) {
            float4 vv = *(const float4*)&Vrow[k * 228 + dd0];
            float vs[4] = {vv.x,vv.y,vv.z,vv.w};
            float pq[4];
            #pragma unroll
            for (int a = 0; a < 4; a++) pq[a] = P[(h * 16 + q0 + a) * 64 + k];
            #pragma unroll
            for (int a = 0; a < 4; a++)
                #pragma unroll
                for (int c = 0; c < 4; c++) acc[a][c] += pq[a] * vs[c];
        }
        #pragma unroll
        for (int c = 0; c < 4; c++)
            *(float4*)&OT[(dd0 + c) * 20 + q0] =
                make_float4(acc[0][c], acc[1][c], acc[2][c], acc[3][c]);
    }
    __syncthreads();

    if (tid < 224) {
        int dg = tid % 56, qg = tid / 56;
        int dd0 = dg * 4, q0 = qg * 4;
        float acc[4][4];
        float4 bb = *(const float4*)&bp[dd0];
        #pragma unroll
        for (int a = 0; a < 4; a++) { acc[a][0]=bb.x; acc[a][1]=bb.y; acc[a][2]=bb.z; acc[a][3]=bb.w; }
        for (int c = 0; c < 224; c++) {
            float4 ov = *(const float4*)&OT[c * 20 + q0];
            float4 wv = *(const float4*)&Wp[c * 224 + dd0];
            float os[4] = {ov.x,ov.y,ov.z,ov.w};
            float ws[4] = {wv.x,wv.y,wv.z,wv.w};
            #pragma unroll
            for (int a = 0; a < 4; a++)
                #pragma unroll
                for (int cc = 0; cc < 4; cc++) acc[a][cc] += os[a] * ws[cc];
        }
        #pragma unroll
        for (int a = 0; a < 4; a++) {
            int q = q0 + a;
            int qy = q >> 2, qx = q & 3;
            int y2 = wy * 4 + qy, x2 = wx * 4 + qx;
            size_t gid = (((size_t)b * 64 + y2) * 64 + x2) * 224 + dd0;
            float4 g = *(float4*)&g_hs[gid];
            g.x += acc[a][0]; g.y += acc[a][1]; g.z += acc[a][2]; g.w += acc[a][3];
            *(float4*)&g_hs[gid] = g;
        }
    }
}

// ---------------------------------------------------------------------------
// K4: out = hs + MLP(LN2(hs)); tf32 tensor cores. 1024 blocks x 256 threads.
// smem: Hs[32][228] fp32 | Xln[32][228] tf32 | Ha[32][900] tf32
// ---------------------------------------------------------------------------
#define HS_STR  228
#define XLN_STR 228
#define HA_STR  900
#define SMEM4   ((32 * HS_STR + 32 * XLN_STR + 32 * HA_STR) * 4)

__global__ void __launch_bounds__(256) k_mlp(
        const float* __restrict__ g2, const float* __restrict__ b2,
        const float* __restrict__ b1, const float* __restrict__ b2m,
        float* __restrict__ out) {
    extern __shared__ float sm[];
    float* Hs  = sm;                       // [t][d] fp32
    float* Xln = sm + 32 * HS_STR;         // [t][c] tf32 bits
    float* Ha  = Xln + 32 * XLN_STR;       // [t][h] tf32 bits

    int t0   = blockIdx.x * 32;
    int tid  = threadIdx.x;
    int warp = tid >> 5, lane = tid & 31;
    int g    = lane >> 2, tig = lane & 3;

    // stage hs rows
    for (int e = tid; e < 32 * 56; e += 256) {
        int t = e / 56, c4 = (e - t * 56) * 4;
        *(float4*)&Hs[t * HS_STR + c4] =
            *(const float4*)&g_hs[(size_t)(t0 + t) * 224 + c4];
    }
    __syncthreads();

    // LN2 (warp per token) -> Xln (tf32-rounded)
    for (int t = warp; t < 32; t += 8) {
        float v[7]; float s = 0.f;
        #pragma unroll
        for (int k = 0; k < 7; k++) { v[k] = Hs[t * HS_STR + lane + 32 * k]; s += v[k]; }
        #pragma unroll
        for (int o = 16; o; o >>= 1) s += __shfl_xor_sync(~0u, s, o);
        float m = s * (1.f / 224.f);
        float q = 0.f;
        #pragma unroll
        for (int k = 0; k < 7; k++) { v[k] -= m; q += v[k] * v[k]; }
        #pragma unroll
        for (int o = 16; o; o >>= 1) q += __shfl_xor_sync(~0u, q, o);
        float rs = rsqrtf(q * (1.f / 224.f) + 1e-6f);
        #pragma unroll
        for (int k = 0; k < 7; k++) {
            int c = lane + 32 * k;
            float val = v[k] * rs * g2[c] + b2[c];
            Xln[t * XLN_STR + c] = __uint_as_float(f2tf32(val));
        }
    }
    __syncthreads();

    // MLP1: warp w owns n-range [w*112, w*112+112), M=32 (2 m-tiles), K=224
    {
        const unsigned* Xb = (const unsigned*)Xln;
        int nb = warp * 112;
        float acc[2][14][4];
        #pragma unroll
        for (int j = 0; j < 14; j++) {
            float bv0 = b1[nb + j * 8 + 2 * tig];
            float bv1 = b1[nb + j * 8 + 2 * tig + 1];
            #pragma unroll
            for (int mt = 0; mt < 2; mt++) {
                acc[mt][j][0] = bv0; acc[mt][j][1] = bv1;
                acc[mt][j][2] = bv0; acc[mt][j][3] = bv1;
            }
        }
        for (int kc = 0; kc < 224; kc += 8) {
            unsigned a[2][4];
            #pragma unroll
            for (int mt = 0; mt < 2; mt++) {
                int r = (mt * 16 + g) * XLN_STR + kc;
                a[mt][0] = Xb[r + tig];
                a[mt][1] = Xb[r + 8 * XLN_STR + tig];
                a[mt][2] = Xb[r + tig + 4];
                a[mt][3] = Xb[r + 8 * XLN_STR + tig + 4];
            }
            unsigned bf[28];
            #pragma unroll
            for (int j = 0; j < 14; j++) {
                int col = nb + j * 8 + g;
                bf[2*j]   = __float_as_uint(g_w1t[(kc + tig) * 896 + col]);
                bf[2*j+1] = __float_as_uint(g_w1t[(kc + tig + 4) * 896 + col]);
            }
            #pragma unroll
            for (int j = 0; j < 14; j++) {
                mma_tf32(acc[0][j], a[0][0], a[0][1], a[0][2], a[0][3], bf[2*j], bf[2*j+1]);
                mma_tf32(acc[1][j], a[1][0], a[1][1], a[1][2], a[1][3], bf[2*j], bf[2*j+1]);
            }
        }
        // GELU + store Ha (tf32-rounded)
        #pragma unroll
        for (int mt = 0; mt < 2; mt++)
            #pragma unroll
            for (int j = 0; j < 14; j++) {
                int h0 = nb + j * 8 + 2 * tig;
                int m0 = mt * 16 + g;
                #pragma unroll
                for (int e = 0; e < 4; e++) {
                    int m = m0 + ((e >= 2) ? 8 : 0);
                    int h = h0 + (e & 1);
                    float aa = acc[mt][j][e];
                    float gv = 0.5f * aa * (1.f + erff(aa * 0.70710678118654752f));
                    Ha[m * HA_STR + h] = __uint_as_float(f2tf32(gv));
                }
            }
    }
    __syncthreads();

    // MLP2: warp w -> m-tile (w&1), n-tiles (w>>1)+4*t, K=896
    {
        const unsigned* Hb = (const unsigned*)Ha;
        int mt = warp & 1, j0 = warp >> 1;
        int m0 = mt * 16;
        float acc[7][4];
        #pragma unroll
        for (int t = 0; t < 7; t++) {
            int n0 = (j0 + 4 * t) * 8;
            float bv0 = b2m[n0 + 2 * tig], bv1 = b2m[n0 + 2 * tig + 1];
            acc[t][0] = bv0; acc[t][1] = bv1; acc[t][2] = bv0; acc[t][3] = bv1;
        }
        #pragma unroll 2
        for (int kc = 0; kc < 896; kc += 8) {
            int r = (m0 + g) * HA_STR + kc;
            unsigned a0 = Hb[r + tig];
            unsigned a1 = Hb[r + 8 * HA_STR + tig];
            unsigned a2 = Hb[r + tig + 4];
            unsigned a3 = Hb[r + 8 * HA_STR + tig + 4];
            unsigned bf[14];
            #pragma unroll
            for (int t = 0; t < 7; t++) {
                int n0 = (j0 + 4 * t) * 8;
                bf[2*t]   = __float_as_uint(g_w2t[(kc + tig) * 224 + n0 + g]);
                bf[2*t+1] = __float_as_uint(g_w2t[(kc + tig + 4) * 224 + n0 + g]);
            }
            #pragma unroll
            for (int t = 0; t < 7; t++)
                mma_tf32(acc[t], a0, a1, a2, a3, bf[2*t], bf[2*t+1]);
        }
        // residual + writeout
        #pragma unroll
        for (int t = 0; t < 7; t++) {
            int n0 = (j0 + 4 * t) * 8;
            #pragma unroll
            for (int e = 0; e < 4; e++) {
                int m = m0 + g + ((e >= 2) ? 8 : 0);
                int n = n0 + 2 * tig + (e & 1);
                out[(size_t)(t0 + m) * 224 + n] = Hs[m * HS_STR + n] + acc[t][e];
            }
        }
    }
}

// ---------------------------------------------------------------------------
extern "C" void kernel_launch(void* const* d_in, const int* in_sizes, int n_in,
                              void* d_out, int out_size) {
    const float* hidden   = (const float*)d_in[0];
    const float* ln1_g    = (const float*)d_in[1];
    const float* ln1_b    = (const float*)d_in[2];
    const float* qkv_w    = (const float*)d_in[3];
    const float* qkv_b    = (const float*)d_in[4];
    const float* aproj_w  = (const float*)d_in[5];
    const float* aproj_b  = (const float*)d_in[6];
    const float* rproj_w  = (const float*)d_in[7];
    const float* rproj_b  = (const float*)d_in[8];
    const float* ln2_g    = (const float*)d_in[9];
    const float* ln2_b    = (const float*)d_in[10];
    const float* mlp1_w   = (const float*)d_in[11];
    const float* mlp1_b   = (const float*)d_in[12];
    const float* mlp2_w   = (const float*)d_in[13];
    const float* mlp2_b   = (const float*)d_in[14];
    float* out = (float*)d_out;

    cudaFuncSetAttribute(k_attn, cudaFuncAttributeMaxDynamicSharedMemorySize, SMEM3);
    cudaFuncSetAttribute(k_mlp,  cudaFuncAttributeMaxDynamicSharedMemorySize, SMEM4);

    k_prep<<<196, 1024>>>(mlp1_w, mlp2_w);
    k_ln1<<<NPIX / 8, 256>>>(hidden, ln1_g, ln1_b);
    k_res<<<NTOK / 8, 448>>>(rproj_w, rproj_b);
    k_attn<<<2048, 448, SMEM3>>>(qkv_w, qkv_b, aproj_w, aproj_b);
    k_mlp<<<1024, 256, SMEM4>>>(ln2_g, ln2_b, mlp1_b, mlp2_b, out);
}

// round 4
// speedup vs baseline: 4.0212x; 1.5425x over previous
#include <cuda_runtime.h>
#include <math.h>

#define DIM   112
#define DIMO  224
#define MLPD  896
#define NPIX  (8*128*128)
#define NTOK  (8*64*64)

// Scratch (device globals; no allocation allowed)
__device__ float g_hs_ln[(size_t)NPIX * DIM];   // LN1 output
__device__ float g_hs[(size_t)NTOK * DIMO];     // residual + attn output
__device__ float g_w1t[224 * 896];              // tf32 mlp1_w
__device__ float g_w2t[896 * 224];              // tf32 mlp2_w
__device__ float g_wqkvt[112 * 672];            // tf32 qkv_w
__device__ float g_wpt[224 * 224];              // tf32 attn_proj_w

__device__ __forceinline__ unsigned f2tf32(float x) {
    unsigned r;
    asm("cvt.rna.tf32.f32 %0, %1;" : "=r"(r) : "f"(x));
    return r;
}
__device__ __forceinline__ float rtf(float x) { return __uint_as_float(f2tf32(x)); }

__device__ __forceinline__ void mma_tf32(float* c,
        unsigned a0, unsigned a1, unsigned a2, unsigned a3,
        unsigned b0, unsigned b1) {
    asm("mma.sync.aligned.m16n8k8.row.col.f32.tf32.tf32.f32 "
        "{%0,%1,%2,%3}, {%4,%5,%6,%7}, {%8,%9}, {%0,%1,%2,%3};"
        : "+f"(c[0]), "+f"(c[1]), "+f"(c[2]), "+f"(c[3])
        : "r"(a0), "r"(a1), "r"(a2), "r"(a3), "r"(b0), "r"(b1));
}

// ---------------------------------------------------------------------------
// K0: round weights to tf32
// ---------------------------------------------------------------------------
__global__ void k_prep(const float* __restrict__ W1, const float* __restrict__ W2,
                       const float* __restrict__ Wqkv, const float* __restrict__ Wp) {
    int i = blockIdx.x * 1024 + threadIdx.x;
    if (i < 224 * 896) {
        g_w1t[i] = rtf(W1[i]);
        g_w2t[i] = rtf(W2[i]);
    }
    if (i < 112 * 672) g_wqkvt[i] = rtf(Wqkv[i]);
    if (i < 224 * 224) g_wpt[i]   = rtf(Wp[i]);
}

// ---------------------------------------------------------------------------
// K1: LayerNorm over DIM=112, warp per pixel
// ---------------------------------------------------------------------------
__global__ void k_ln1(const float* __restrict__ x,
                      const float* __restrict__ g,
                      const float* __restrict__ b) {
    int pix  = blockIdx.x * 8 + (threadIdx.x >> 5);
    int lane = threadIdx.x & 31;
    const float* px = x + (size_t)pix * DIM;
    float v0 = px[lane], v1 = px[lane + 32], v2 = px[lane + 64];
    float v3 = (lane < 16) ? px[lane + 96] : 0.f;
    float s = v0 + v1 + v2 + v3;
    #pragma unroll
    for (int o = 16; o; o >>= 1) s += __shfl_xor_sync(~0u, s, o);
    float m = s * (1.f / 112.f);
    float d0 = v0 - m, d1 = v1 - m, d2 = v2 - m;
    float d3 = (lane < 16) ? v3 - m : 0.f;
    float q = d0*d0 + d1*d1 + d2*d2 + d3*d3;
    #pragma unroll
    for (int o = 16; o; o >>= 1) q += __shfl_xor_sync(~0u, q, o);
    float rs = rsqrtf(q * (1.f / 112.f) + 1e-6f);
    float* po = g_hs_ln + (size_t)pix * DIM;
    po[lane]      = d0 * rs * g[lane]      + b[lane];
    po[lane + 32] = d1 * rs * g[lane + 32] + b[lane + 32];
    po[lane + 64] = d2 * rs * g[lane + 64] + b[lane + 64];
    if (lane < 16) po[lane + 96] = d3 * rs * g[lane + 96] + b[lane + 96];
}

// ---------------------------------------------------------------------------
// K2: residual = maxpool2(hs_ln @ res_proj_w + b) -> g_hs  (fp32)
// ---------------------------------------------------------------------------
__global__ void __launch_bounds__(448) k_res(const float* __restrict__ W,
                                             const float* __restrict__ bias) {
    __shared__ float Xrt[112 * 36];
    int t0  = blockIdx.x * 8;
    int b   = t0 >> 12;
    int rem = t0 & 4095;
    int y2  = rem >> 6;
    int x2b = rem & 63;
    int tid = threadIdx.x;

    for (int e = tid; e < 32 * 28; e += 448) {
        int p = e / 28, c4 = (e - p * 28) * 4;
        int j = p >> 2, cell = p & 3;
        int dy = cell >> 1, dx = cell & 1;
        int y = 2 * y2 + dy, x = 2 * (x2b + j) + dx;
        float4 v = *(const float4*)&g_hs_ln[(((size_t)b * 128 + y) * 128 + x) * 112 + c4];
        Xrt[(c4 + 0) * 36 + p] = v.x;
        Xrt[(c4 + 1) * 36 + p] = v.y;
        Xrt[(c4 + 2) * 36 + p] = v.z;
        Xrt[(c4 + 3) * 36 + p] = v.w;
    }
    __syncthreads();

    int j  = tid / 56;
    int d0 = (tid % 56) * 4;
    float acc[4][4];
    #pragma unroll
    for (int a = 0; a < 4; a++)
        #pragma unroll
        for (int c = 0; c < 4; c++) acc[a][c] = 0.f;

    for (int c = 0; c < 112; c++) {
        float4 xv = *(const float4*)&Xrt[c * 36 + j * 4];
        float4 wv = *(const float4*)&W[c * 224 + d0];
        float xs[4] = {xv.x, xv.y, xv.z, xv.w};
        float ws[4] = {wv.x, wv.y, wv.z, wv.w};
        #pragma unroll
        for (int a = 0; a < 4; a++)
            #pragma unroll
            for (int cc = 0; cc < 4; cc++) acc[a][cc] += xs[a] * ws[cc];
    }
    float4 bb = *(const float4*)&bias[d0];
    float4 r;
    r.x = fmaxf(fmaxf(acc[0][0], acc[1][0]), fmaxf(acc[2][0], acc[3][0])) + bb.x;
    r.y = fmaxf(fmaxf(acc[0][1], acc[1][1]), fmaxf(acc[2][1], acc[3][1])) + bb.y;
    r.z = fmaxf(fmaxf(acc[0][2], acc[1][2]), fmaxf(acc[2][2], acc[3][2])) + bb.z;
    r.w = fmaxf(fmaxf(acc[0][3], acc[1][3]), fmaxf(acc[2][3], acc[3][3])) + bb.w;
    *(float4*)&g_hs[(size_t)(t0 + j) * 224 + d0] = r;
}

// ---------------------------------------------------------------------------
// K3: per-window attention, full tf32 tensor-core path.
// 2048 blocks x 448 threads (14 warps).
// smem (floats): Xs[64][116] | Kt[224][72] | Vrow[64][232] | Qraw[64][232] | Qt[16][232]
// P (4*16 x 72) aliases Xs; Ot (16 x 232) aliases Qraw.
// ---------------------------------------------------------------------------
#define XS_STR  116
#define KT_STR  72
#define VR_STR  232
#define QR_STR  232
#define QT_STR  232
#define P_STR   72
#define OT_STR  232
#define XS_N    (64 * XS_STR)    // 7424
#define KT_N    (224 * KT_STR)   // 16128
#define VR_N    (64 * VR_STR)    // 14848
#define QR_N    (64 * QR_STR)    // 14848
#define QT_N    (16 * QT_STR)    // 3712
#define SMEM3   ((XS_N + KT_N + VR_N + QR_N + QT_N) * 4)   // 227840 B

__global__ void __launch_bounds__(448) k_attn(
        const float* __restrict__ bqkv, const float* __restrict__ bp) {
    extern __shared__ float sm[];
    float* Xs   = sm;                 // tf32-rounded window [t][c]
    float* Kt   = Xs + XS_N;          // [d][t]
    float* Vrow = Kt + KT_N;          // [t][d]
    float* Qraw = Vrow + VR_N;        // [t][d]
    float* Qt   = Qraw + QR_N;        // [q][d]
    float* P    = Xs;                 // [h*16+q][t] (alias)
    float* Ot   = Qraw;               // [q][d] (alias)

    int wi = blockIdx.x;
    int b  = wi >> 8;
    int r  = wi & 255;
    int wy = r >> 4, wx = r & 15;
    int tid  = threadIdx.x;
    int warp = tid >> 5, lane = tid & 31;
    int g = lane >> 2, tig = lane & 3;

    // ---- stage window, tf32-rounded ----
    for (int e = tid; e < 64 * 28; e += 448) {
        int t = e / 28, c4 = (e - t * 28) * 4;
        int ty = t >> 3, tx = t & 7;
        int y = wy * 8 + ty, x = wx * 8 + tx;
        float4 v = *(const float4*)&g_hs_ln[(((size_t)b * 128 + y) * 128 + x) * 112 + c4];
        *(float4*)&Xs[t * XS_STR + c4] =
            make_float4(rtf(v.x), rtf(v.y), rtf(v.z), rtf(v.w));
    }
    __syncthreads();

    // ---- QKV GEMM: M=64, N=672, K=112. warp n-slice = 48 cols ----
    {
        const unsigned* Xb = (const unsigned*)Xs;
        int wbase = warp * 48;
        float acc[4][6][4];
        #pragma unroll
        for (int j = 0; j < 6; j++) {
            int col = wbase + j * 8;
            float bv0 = bqkv[col + 2 * tig];
            float bv1 = bqkv[col + 2 * tig + 1];
            #pragma unroll
            for (int mt = 0; mt < 4; mt++) {
                acc[mt][j][0] = bv0; acc[mt][j][1] = bv1;
                acc[mt][j][2] = bv0; acc[mt][j][3] = bv1;
            }
        }
        for (int kc = 0; kc < 112; kc += 8) {
            unsigned a[4][4];
            #pragma unroll
            for (int mt = 0; mt < 4; mt++) {
                int r0 = (mt * 16 + g) * XS_STR + kc;
                int r1 = (mt * 16 + 8 + g) * XS_STR + kc;
                a[mt][0] = Xb[r0 + tig];
                a[mt][1] = Xb[r1 + tig];
                a[mt][2] = Xb[r0 + tig + 4];
                a[mt][3] = Xb[r1 + tig + 4];
            }
            #pragma unroll
            for (int j = 0; j < 6; j++) {
                int col = wbase + j * 8 + g;
                unsigned b0 = __float_as_uint(g_wqkvt[(kc + tig) * 672 + col]);
                unsigned b1 = __float_as_uint(g_wqkvt[(kc + tig + 4) * 672 + col]);
                #pragma unroll
                for (int mt = 0; mt < 4; mt++)
                    mma_tf32(acc[mt][j], a[mt][0], a[mt][1], a[mt][2], a[mt][3], b0, b1);
            }
        }
        // routed stores, tf32-rounded
        #pragma unroll
        for (int j = 0; j < 6; j++) {
            int col = wbase + j * 8;
            int mat = col / 224;
            int lc  = col - mat * 224;
            #pragma unroll
            for (int mt = 0; mt < 4; mt++) {
                int t0r = mt * 16 + g;
                float* a = acc[mt][j];
                if (mat == 1) {
                    Kt[(lc + 2*tig)     * KT_STR + t0r]     = rtf(a[0]);
                    Kt[(lc + 2*tig + 1) * KT_STR + t0r]     = rtf(a[1]);
                    Kt[(lc + 2*tig)     * KT_STR + t0r + 8] = rtf(a[2]);
                    Kt[(lc + 2*tig + 1) * KT_STR + t0r + 8] = rtf(a[3]);
                } else {
                    float* dst = (mat == 0) ? Qraw : Vrow;
                    dst[t0r * 232 + lc + 2*tig]           = rtf(a[0]);
                    dst[t0r * 232 + lc + 2*tig + 1]       = rtf(a[1]);
                    dst[(t0r + 8) * 232 + lc + 2*tig]     = rtf(a[2]);
                    dst[(t0r + 8) * 232 + lc + 2*tig + 1] = rtf(a[3]);
                }
            }
        }
    }
    __syncthreads();

    // ---- Q pooling: Qt[q][d] = max over 2x2 token cell ----
    for (int e = tid; e < 16 * 224; e += 448) {
        int q = e / 224, d = e - q * 224;
        int qy = q >> 2, qx = q & 3;
        int t00 = (2 * qy) * 8 + 2 * qx;
        float m = fmaxf(fmaxf(Qraw[t00 * QR_STR + d],       Qraw[(t00 + 1) * QR_STR + d]),
                        fmaxf(Qraw[(t00 + 8) * QR_STR + d], Qraw[(t00 + 9) * QR_STR + d]));
        Qt[q * QT_STR + d] = m;
    }
    __syncthreads();

    // ---- scores: per head 16x64x56 -> P (aliases Xs) ----
    const float scale = 0.13363062095621219f;   // 56^-0.5
    if (warp < 8) {
        int h = warp >> 1, nh = warp & 1;
        const unsigned* Qb = (const unsigned*)Qt;
        const unsigned* Kb = (const unsigned*)Kt;
        float acc[4][4];
        #pragma unroll
        for (int j = 0; j < 4; j++)
            #pragma unroll
            for (int e = 0; e < 4; e++) acc[j][e] = 0.f;
        #pragma unroll
        for (int kc = 0; kc < 56; kc += 8) {
            int kd = h * 56 + kc;
            unsigned a0 = Qb[g * QT_STR + kd + tig];
            unsigned a1 = Qb[(g + 8) * QT_STR + kd + tig];
            unsigned a2 = Qb[g * QT_STR + kd + tig + 4];
            unsigned a3 = Qb[(g + 8) * QT_STR + kd + tig + 4];
            #pragma unroll
            for (int j = 0; j < 4; j++) {
                int n0 = nh * 32 + j * 8;
                unsigned b0 = Kb[(kd + tig) * KT_STR + n0 + g];
                unsigned b1 = Kb[(kd + tig + 4) * KT_STR + n0 + g];
                mma_tf32(acc[j], a0, a1, a2, a3, b0, b1);
            }
        }
        #pragma unroll
        for (int j = 0; j < 4; j++) {
            int n0 = nh * 32 + j * 8;
            P[(h * 16 + g) * P_STR + n0 + 2*tig]         = acc[j][0] * scale;
            P[(h * 16 + g) * P_STR + n0 + 2*tig + 1]     = acc[j][1] * scale;
            P[(h * 16 + g + 8) * P_STR + n0 + 2*tig]     = acc[j][2] * scale;
            P[(h * 16 + g + 8) * P_STR + n0 + 2*tig + 1] = acc[j][3] * scale;
        }
    }
    __syncthreads();

    // ---- softmax over 64 rows of 64; write back tf32-rounded ----
    for (int rr = warp; rr < 64; rr += 14) {
        float* row = P + rr * P_STR;
        float a = row[lane], c2 = row[lane + 32];
        float mx = fmaxf(a, c2);
        #pragma unroll
        for (int o = 16; o; o >>= 1) mx = fmaxf(mx, __shfl_xor_sync(~0u, mx, o));
        a = __expf(a - mx); c2 = __expf(c2 - mx);
        float s = a + c2;
        #pragma unroll
        for (int o = 16; o; o >>= 1) s += __shfl_xor_sync(~0u, s, o);
        float inv = 1.f / s;
        row[lane]      = rtf(a * inv);
        row[lane + 32] = rtf(c2 * inv);
    }
    __syncthreads();

    // ---- PV: per head 16x56x64 -> Ot (aliases Qraw) ----
    {
        const unsigned* Pb = (const unsigned*)P;
        const unsigned* Vb = (const unsigned*)Vrow;
        #pragma unroll
        for (int ui = 0; ui < 2; ui++) {
            int u = warp * 2 + ui;   // 0..27
            int h = u / 7, j = u - h * 7;
            int n0 = h * 56 + j * 8;
            float acc[4] = {0.f, 0.f, 0.f, 0.f};
            #pragma unroll
            for (int kc = 0; kc < 64; kc += 8) {
                unsigned a0 = Pb[(h * 16 + g) * P_STR + kc + tig];
                unsigned a1 = Pb[(h * 16 + g + 8) * P_STR + kc + tig];
                unsigned a2 = Pb[(h * 16 + g) * P_STR + kc + tig + 4];
                unsigned a3 = Pb[(h * 16 + g + 8) * P_STR + kc + tig + 4];
                unsigned b0 = Vb[(kc + tig) * VR_STR + n0 + g];
                unsigned b1 = Vb[(kc + tig + 4) * VR_STR + n0 + g];
                mma_tf32(acc, a0, a1, a2, a3, b0, b1);
            }
            __syncthreads();   // ensure P fully read before Ot overwrite... (no-op safety)
            Ot[g * OT_STR + n0 + 2*tig]           = rtf(acc[0]);
            Ot[g * OT_STR + n0 + 2*tig + 1]       = rtf(acc[1]);
            Ot[(g + 8) * OT_STR + n0 + 2*tig]     = rtf(acc[2]);
            Ot[(g + 8) * OT_STR + n0 + 2*tig + 1] = rtf(acc[3]);
        }
    }
    __syncthreads();

    // ---- attn_proj + residual accumulate: 16x224x224 ----
    {
        const unsigned* Ob = (const unsigned*)Ot;
        int n0w = warp * 16;
        float acc[2][4];
        #pragma unroll
        for (int j = 0; j < 2; j++) {
            int col = n0w + j * 8;
            float bv0 = bp[col + 2 * tig];
            float bv1 = bp[col + 2 * tig + 1];
            acc[j][0] = bv0; acc[j][1] = bv1; acc[j][2] = bv0; acc[j][3] = bv1;
        }
        #pragma unroll 4
        for (int kc = 0; kc < 224; kc += 8) {
            unsigned a0 = Ob[g * OT_STR + kc + tig];
            unsigned a1 = Ob[(g + 8) * OT_STR + kc + tig];
            unsigned a2 = Ob[g * OT_STR + kc + tig + 4];
            unsigned a3 = Ob[(g + 8) * OT_STR + kc + tig + 4];
            #pragma unroll
            for (int j = 0; j < 2; j++) {
                int n0 = n0w + j * 8;
                unsigned b0 = __float_as_uint(g_wpt[(kc + tig) * 224 + n0 + g]);
                unsigned b1 = __float_as_uint(g_wpt[(kc + tig + 4) * 224 + n0 + g]);
                mma_tf32(acc[j], a0, a1, a2, a3, b0, b1);
            }
        }
        #pragma unroll
        for (int j = 0; j < 2; j++) {
            #pragma unroll
            for (int e = 0; e < 4; e++) {
                int q = g + ((e >= 2) ? 8 : 0);
                int d = n0w + j * 8 + 2 * tig + (e & 1);
                int qy = q >> 2, qx = q & 3;
                int y2 = wy * 4 + qy, x2 = wx * 4 + qx;
                size_t gid = (((size_t)b * 64 + y2) * 64 + x2) * 224 + d;
                g_hs[gid] += acc[j][e];
            }
        }
    }
}

// ---------------------------------------------------------------------------
// K4: out = hs + MLP(LN2(hs)); tf32 tensor cores. 1024 blocks x 256 threads.
// ---------------------------------------------------------------------------
#define HS_STR  228
#define XLN_STR 228
#define HA_STR  900
#define SMEM4   ((32 * HS_STR + 32 * XLN_STR + 32 * HA_STR) * 4)

__global__ void __launch_bounds__(256) k_mlp(
        const float* __restrict__ g2, const float* __restrict__ b2,
        const float* __restrict__ b1, const float* __restrict__ b2m,
        float* __restrict__ out) {
    extern __shared__ float sm[];
    float* Hs  = sm;
    float* Xln = sm + 32 * HS_STR;
    float* Ha  = Xln + 32 * XLN_STR;

    int t0   = blockIdx.x * 32;
    int tid  = threadIdx.x;
    int warp = tid >> 5, lane = tid & 31;
    int g    = lane >> 2, tig = lane & 3;

    for (int e = tid; e < 32 * 56; e += 256) {
        int t = e / 56, c4 = (e - t * 56) * 4;
        *(float4*)&Hs[t * HS_STR + c4] =
            *(const float4*)&g_hs[(size_t)(t0 + t) * 224 + c4];
    }
    __syncthreads();

    for (int t = warp; t < 32; t += 8) {
        float v[7]; float s = 0.f;
        #pragma unroll
        for (int k = 0; k < 7; k++) { v[k] = Hs[t * HS_STR + lane + 32 * k]; s += v[k]; }
        #pragma unroll
        for (int o = 16; o; o >>= 1) s += __shfl_xor_sync(~0u, s, o);
        float m = s * (1.f / 224.f);
        float q = 0.f;
        #pragma unroll
        for (int k = 0; k < 7; k++) { v[k] -= m; q += v[k] * v[k]; }
        #pragma unroll
        for (int o = 16; o; o >>= 1) q += __shfl_xor_sync(~0u, q, o);
        float rs = rsqrtf(q * (1.f / 224.f) + 1e-6f);
        #pragma unroll
        for (int k = 0; k < 7; k++) {
            int c = lane + 32 * k;
            float val = v[k] * rs * g2[c] + b2[c];
            Xln[t * XLN_STR + c] = rtf(val);
        }
    }
    __syncthreads();

    {
        const unsigned* Xb = (const unsigned*)Xln;
        int nb = warp * 112;
        float acc[2][14][4];
        #pragma unroll
        for (int j = 0; j < 14; j++) {
            float bv0 = b1[nb + j * 8 + 2 * tig];
            float bv1 = b1[nb + j * 8 + 2 * tig + 1];
            #pragma unroll
            for (int mt = 0; mt < 2; mt++) {
                acc[mt][j][0] = bv0; acc[mt][j][1] = bv1;
                acc[mt][j][2] = bv0; acc[mt][j][3] = bv1;
            }
        }
        for (int kc = 0; kc < 224; kc += 8) {
            unsigned a[2][4];
            #pragma unroll
            for (int mt = 0; mt < 2; mt++) {
                int r = (mt * 16 + g) * XLN_STR + kc;
                a[mt][0] = Xb[r + tig];
                a[mt][1] = Xb[r + 8 * XLN_STR + tig];
                a[mt][2] = Xb[r + tig + 4];
                a[mt][3] = Xb[r + 8 * XLN_STR + tig + 4];
            }
            unsigned bf[28];
            #pragma unroll
            for (int j = 0; j < 14; j++) {
                int col = nb + j * 8 + g;
                bf[2*j]   = __float_as_uint(g_w1t[(kc + tig) * 896 + col]);
                bf[2*j+1] = __float_as_uint(g_w1t[(kc + tig + 4) * 896 + col]);
            }
            #pragma unroll
            for (int j = 0; j < 14; j++) {
                mma_tf32(acc[0][j], a[0][0], a[0][1], a[0][2], a[0][3], bf[2*j], bf[2*j+1]);
                mma_tf32(acc[1][j], a[1][0], a[1][1], a[1][2], a[1][3], bf[2*j], bf[2*j+1]);
            }
        }
        #pragma unroll
        for (int mt = 0; mt < 2; mt++)
            #pragma unroll
            for (int j = 0; j < 14; j++) {
                int h0 = nb + j * 8 + 2 * tig;
                int m0 = mt * 16 + g;
                #pragma unroll
                for (int e = 0; e < 4; e++) {
                    int m = m0 + ((e >= 2) ? 8 : 0);
                    int h = h0 + (e & 1);
                    float aa = acc[mt][j][e];
                    float gv = 0.5f * aa * (1.f + erff(aa * 0.70710678118654752f));
                    Ha[m * HA_STR + h] = rtf(gv);
                }
            }
    }
    __syncthreads();

    {
        const unsigned* Hb = (const unsigned*)Ha;
        int mt = warp & 1, j0 = warp >> 1;
        int m0 = mt * 16;
        float acc[7][4];
        #pragma unroll
        for (int t = 0; t < 7; t++) {
            int n0 = (j0 + 4 * t) * 8;
            float bv0 = b2m[n0 + 2 * tig], bv1 = b2m[n0 + 2 * tig + 1];
            acc[t][0] = bv0; acc[t][1] = bv1; acc[t][2] = bv0; acc[t][3] = bv1;
        }
        #pragma unroll 2
        for (int kc = 0; kc < 896; kc += 8) {
            int r = (m0 + g) * HA_STR + kc;
            unsigned a0 = Hb[r + tig];
            unsigned a1 = Hb[r + 8 * HA_STR + tig];
            unsigned a2 = Hb[r + tig + 4];
            unsigned a3 = Hb[r + 8 * HA_STR + tig + 4];
            unsigned bf[14];
            #pragma unroll
            for (int t = 0; t < 7; t++) {
                int n0 = (j0 + 4 * t) * 8;
                bf[2*t]   = __float_as_uint(g_w2t[(kc + tig) * 224 + n0 + g]);
                bf[2*t+1] = __float_as_uint(g_w2t[(kc + tig + 4) * 224 + n0 + g]);
            }
            #pragma unroll
            for (int t = 0; t < 7; t++)
                mma_tf32(acc[t], a0, a1, a2, a3, bf[2*t], bf[2*t+1]);
        }
        #pragma unroll
        for (int t = 0; t < 7; t++) {
            int n0 = (j0 + 4 * t) * 8;
            #pragma unroll
            for (int e = 0; e < 4; e++) {
                int m = m0 + g + ((e >= 2) ? 8 : 0);
                int n = n0 + 2 * tig + (e & 1);
                out[(size_t)(t0 + m) * 224 + n] = Hs[m * HS_STR + n] + acc[t][e];
            }
        }
    }
}

// ---------------------------------------------------------------------------
extern "C" void kernel_launch(void* const* d_in, const int* in_sizes, int n_in,
                              void* d_out, int out_size) {
    const float* hidden   = (const float*)d_in[0];
    const float* ln1_g    = (const float*)d_in[1];
    const float* ln1_b    = (const float*)d_in[2];
    const float* qkv_w    = (const float*)d_in[3];
    const float* qkv_b    = (const float*)d_in[4];
    const float* aproj_w  = (const float*)d_in[5];
    const float* aproj_b  = (const float*)d_in[6];
    const float* rproj_w  = (const float*)d_in[7];
    const float* rproj_b  = (const float*)d_in[8];
    const float* ln2_g    = (const float*)d_in[9];
    const float* ln2_b    = (const float*)d_in[10];
    const float* mlp1_w   = (const float*)d_in[11];
    const float* mlp1_b   = (const float*)d_in[12];
    const float* mlp2_w   = (const float*)d_in[13];
    const float* mlp2_b   = (const float*)d_in[14];
    float* out = (float*)d_out;

    cudaFuncSetAttribute(k_attn, cudaFuncAttributeMaxDynamicSharedMemorySize, SMEM3);
    cudaFuncSetAttribute(k_mlp,  cudaFuncAttributeMaxDynamicSharedMemorySize, SMEM4);

    k_prep<<<196, 1024>>>(mlp1_w, mlp2_w, qkv_w, aproj_w);
    k_ln1<<<NPIX / 8, 256>>>(hidden, ln1_g, ln1_b);
    k_res<<<NTOK / 8, 448>>>(rproj_w, rproj_b);
    k_attn<<<2048, 448, SMEM3>>>(qkv_b, aproj_b);
    k_mlp<<<1024, 256, SMEM4>>>(ln2_g, ln2_b, mlp1_b, mlp2_b, out);
}

// round 5
// speedup vs baseline: 4.5300x; 1.1265x over previous
#include <cuda_runtime.h>
#include <math.h>

#define NTOK  (8*64*64)

// Scratch (device globals)
__device__ float g_hs[(size_t)NTOK * 224];   // residual + attn output
__device__ float g_w1t[224 * 896];           // tf32 mlp1_w
__device__ float g_w2t[896 * 224];           // tf32 mlp2_w
__device__ float g_wbig[112 * 896];          // tf32 [qkv_w | res_proj_w]
__device__ float g_wpt[224 * 224];           // tf32 attn_proj_w
__device__ float g_bbig[896];                // [qkv_b | res_proj_b]

__device__ __forceinline__ unsigned f2tf32(float x) {
    unsigned r;
    asm("cvt.rna.tf32.f32 %0, %1;" : "=r"(r) : "f"(x));
    return r;
}
__device__ __forceinline__ float rtf(float x) { return __uint_as_float(f2tf32(x)); }

__device__ __forceinline__ void mma_tf32(float* c,
        unsigned a0, unsigned a1, unsigned a2, unsigned a3,
        unsigned b0, unsigned b1) {
    asm("mma.sync.aligned.m16n8k8.row.col.f32.tf32.tf32.f32 "
        "{%0,%1,%2,%3}, {%4,%5,%6,%7}, {%8,%9}, {%0,%1,%2,%3};"
        : "+f"(c[0]), "+f"(c[1]), "+f"(c[2]), "+f"(c[3])
        : "r"(a0), "r"(a1), "r"(a2), "r"(a3), "r"(b0), "r"(b1));
}

// ---------------------------------------------------------------------------
// K0: round weights to tf32, build combined [qkv|res] weight + bias
// ---------------------------------------------------------------------------
__global__ void k_prep(const float* __restrict__ W1,   const float* __restrict__ W2,
                       const float* __restrict__ Wqkv, const float* __restrict__ Wrp,
                       const float* __restrict__ Wp,
                       const float* __restrict__ bqkv, const float* __restrict__ brp) {
    int i = blockIdx.x * 1024 + threadIdx.x;
    if (i < 224 * 896) { g_w1t[i] = rtf(W1[i]); g_w2t[i] = rtf(W2[i]); }
    if (i < 112 * 896) {
        int r = i / 896, c = i - r * 896;
        float v = (c < 672) ? Wqkv[r * 672 + c] : Wrp[r * 224 + (c - 672)];
        g_wbig[i] = rtf(v);
    }
    if (i < 224 * 224) g_wpt[i] = rtf(Wp[i]);
    if (i < 896) g_bbig[i] = (i < 672) ? bqkv[i] : brp[i - 672];
}

// ---------------------------------------------------------------------------
// K3: fused LN1 + QKV/R GEMM + pooling + attention + proj + residual
// 2048 blocks x 448 threads (14 warps)
// smem: Xs[64][116] | Kt[224][76] | Vrow[64][236] | Qt[16][236] | Rt[16][236]
// P (64x76) aliases Xs; Ot (16x236) aliases Qt.
// ---------------------------------------------------------------------------
#define XS_STR 116
#define KT_STR 76
#define VR_STR 236
#define QT_STR 236
#define RT_STR 236
#define OT_STR 236
#define P_STR  76
#define XS_N (64 * XS_STR)     // 7424
#define KT_N (224 * KT_STR)    // 17024
#define VR_N (64 * VR_STR)     // 15104
#define QT_N (16 * QT_STR)     // 3776
#define RT_N (16 * RT_STR)     // 3776
#define SMEM3 ((XS_N + KT_N + VR_N + QT_N + RT_N) * 4)   // 188416 B

__global__ void __launch_bounds__(448) k_attn(
        const float* __restrict__ hidden,
        const float* __restrict__ ln1g, const float* __restrict__ ln1b,
        const float* __restrict__ bp) {
    extern __shared__ float sm[];
    float* Xs   = sm;
    float* Kt   = Xs + XS_N;
    float* Vrow = Kt + KT_N;
    float* Qt   = Vrow + VR_N;
    float* Rt   = Qt + QT_N;
    float* P    = Xs;    // alias (X dead after QKV)
    float* Ot   = Qt;    // alias (Qt dead after scores)

    int wi = blockIdx.x;
    int b  = wi >> 8;
    int r  = wi & 255;
    int wy = r >> 4, wx = r & 15;
    int tid  = threadIdx.x;
    int warp = tid >> 5, lane = tid & 31;
    int g = lane >> 2, tig = lane & 3;

    // ---- stage raw window ----
    for (int e = tid; e < 64 * 28; e += 448) {
        int t = e / 28, c4 = (e - t * 28) * 4;
        int y = wy * 8 + (t >> 3), x = wx * 8 + (t & 7);
        *(float4*)&Xs[t * XS_STR + c4] =
            *(const float4*)&hidden[(((size_t)b * 128 + y) * 128 + x) * 112 + c4];
    }
    __syncthreads();

    // ---- LN1 in place (warp per token), tf32-rounded ----
    {
        float gg0 = ln1g[lane], gg1 = ln1g[lane + 32], gg2 = ln1g[lane + 64];
        float bb0 = ln1b[lane], bb1 = ln1b[lane + 32], bb2 = ln1b[lane + 64];
        float gg3 = 0.f, bb3 = 0.f;
        if (lane < 16) { gg3 = ln1g[lane + 96]; bb3 = ln1b[lane + 96]; }
        for (int t = warp; t < 64; t += 14) {
            float* row = Xs + t * XS_STR;
            float v0 = row[lane], v1 = row[lane + 32], v2 = row[lane + 64];
            float v3 = (lane < 16) ? row[lane + 96] : 0.f;
            float s = v0 + v1 + v2 + v3;
            #pragma unroll
            for (int o = 16; o; o >>= 1) s += __shfl_xor_sync(~0u, s, o);
            float m = s * (1.f / 112.f);
            float d0 = v0 - m, d1 = v1 - m, d2 = v2 - m;
            float d3 = (lane < 16) ? v3 - m : 0.f;
            float q = d0*d0 + d1*d1 + d2*d2 + d3*d3;
            #pragma unroll
            for (int o = 16; o; o >>= 1) q += __shfl_xor_sync(~0u, q, o);
            float rs = rsqrtf(q * (1.f / 112.f) + 1e-6f);
            row[lane]      = rtf(d0 * rs * gg0 + bb0);
            row[lane + 32] = rtf(d1 * rs * gg1 + bb1);
            row[lane + 64] = rtf(d2 * rs * gg2 + bb2);
            if (lane < 16) row[lane + 96] = rtf(d3 * rs * gg3 + bb3);
        }
    }
    __syncthreads();

    // ---- QKV+R GEMM: M=64, N=896, K=112; warp n-slice 64, two j-passes of 4 ----
    {
        const unsigned* Xb = (const unsigned*)Xs;
        const unsigned* Wb = (const unsigned*)g_wbig;
        #pragma unroll
        for (int pass = 0; pass < 2; pass++) {
            int colbase = warp * 64 + pass * 32;
            float acc[4][4][4];
            #pragma unroll
            for (int j = 0; j < 4; j++) {
                int col = colbase + j * 8;
                float bv0 = g_bbig[col + 2 * tig];
                float bv1 = g_bbig[col + 2 * tig + 1];
                #pragma unroll
                for (int mt = 0; mt < 4; mt++) {
                    acc[mt][j][0] = bv0; acc[mt][j][1] = bv1;
                    acc[mt][j][2] = bv0; acc[mt][j][3] = bv1;
                }
            }
            for (int kc = 0; kc < 112; kc += 8) {
                unsigned a[4][4];
                #pragma unroll
                for (int mt = 0; mt < 4; mt++) {
                    int r0 = (mt * 16 + g) * XS_STR + kc;
                    int r1 = r0 + 8 * XS_STR;
                    a[mt][0] = Xb[r0 + tig];
                    a[mt][1] = Xb[r1 + tig];
                    a[mt][2] = Xb[r0 + tig + 4];
                    a[mt][3] = Xb[r1 + tig + 4];
                }
                #pragma unroll
                for (int j = 0; j < 4; j++) {
                    int col = colbase + j * 8 + g;
                    unsigned b0 = Wb[(kc + tig) * 896 + col];
                    unsigned b1 = Wb[(kc + tig + 4) * 896 + col];
                    #pragma unroll
                    for (int mt = 0; mt < 4; mt++)
                        mma_tf32(acc[mt][j], a[mt][0], a[mt][1], a[mt][2], a[mt][3], b0, b1);
                }
            }
            // routed stores (uniform branch per warp/j)
            #pragma unroll
            for (int j = 0; j < 4; j++) {
                int col = colbase + j * 8;
                int mat = col / 224;
                int lc  = col - mat * 224;
                if (mat == 1) {            // K -> Kt[d][t]
                    #pragma unroll
                    for (int mt = 0; mt < 4; mt++) {
                        int t0r = mt * 16 + g;
                        Kt[(lc + 2*tig)     * KT_STR + t0r]     = rtf(acc[mt][j][0]);
                        Kt[(lc + 2*tig + 1) * KT_STR + t0r]     = rtf(acc[mt][j][1]);
                        Kt[(lc + 2*tig)     * KT_STR + t0r + 8] = rtf(acc[mt][j][2]);
                        Kt[(lc + 2*tig + 1) * KT_STR + t0r + 8] = rtf(acc[mt][j][3]);
                    }
                } else if (mat == 2) {     // V -> Vrow[t][d]
                    #pragma unroll
                    for (int mt = 0; mt < 4; mt++) {
                        int t0r = mt * 16 + g;
                        Vrow[t0r * VR_STR + lc + 2*tig]           = rtf(acc[mt][j][0]);
                        Vrow[t0r * VR_STR + lc + 2*tig + 1]       = rtf(acc[mt][j][1]);
                        Vrow[(t0r + 8) * VR_STR + lc + 2*tig]     = rtf(acc[mt][j][2]);
                        Vrow[(t0r + 8) * VR_STR + lc + 2*tig + 1] = rtf(acc[mt][j][3]);
                    }
                } else {                   // Q (mat 0) or R (mat 3): 2x2 pool in regs
                    float* dst = (mat == 0) ? Qt : Rt;
                    #pragma unroll
                    for (int mt = 0; mt < 4; mt++) {
                        float m0 = fmaxf(acc[mt][j][0], acc[mt][j][2]);  // rows g, g+8
                        float m1 = fmaxf(acc[mt][j][1], acc[mt][j][3]);
                        m0 = fmaxf(m0, __shfl_xor_sync(~0u, m0, 4));     // lanes g ^ 1
                        m1 = fmaxf(m1, __shfl_xor_sync(~0u, m1, 4));
                        if (!(g & 1)) {
                            int q = mt * 4 + (g >> 1);
                            if (mat == 0) {
                                Qt[q * QT_STR + lc + 2*tig]     = rtf(m0);
                                Qt[q * QT_STR + lc + 2*tig + 1] = rtf(m1);
                            } else {
                                Rt[q * RT_STR + lc + 2*tig]     = m0;
                                Rt[q * RT_STR + lc + 2*tig + 1] = m1;
                            }
                        }
                    }
                    (void)dst;
                }
            }
        }
    }
    __syncthreads();

    // ---- scores: per head 16x64x56 -> P (aliases Xs) ----
    const float scale = 0.13363062095621219f;   // 56^-0.5
    if (warp < 8) {
        int h = warp >> 1, nh = warp & 1;
        const unsigned* Qb = (const unsigned*)Qt;
        const unsigned* Kb = (const unsigned*)Kt;
        float acc[4][4];
        #pragma unroll
        for (int j = 0; j < 4; j++)
            #pragma unroll
            for (int e = 0; e < 4; e++) acc[j][e] = 0.f;
        #pragma unroll
        for (int kc = 0; kc < 56; kc += 8) {
            int kd = h * 56 + kc;
            unsigned a0 = Qb[g * QT_STR + kd + tig];
            unsigned a1 = Qb[(g + 8) * QT_STR + kd + tig];
            unsigned a2 = Qb[g * QT_STR + kd + tig + 4];
            unsigned a3 = Qb[(g + 8) * QT_STR + kd + tig + 4];
            #pragma unroll
            for (int j = 0; j < 4; j++) {
                int n0 = nh * 32 + j * 8;
                unsigned b0 = Kb[(kd + tig) * KT_STR + n0 + g];
                unsigned b1 = Kb[(kd + tig + 4) * KT_STR + n0 + g];
                mma_tf32(acc[j], a0, a1, a2, a3, b0, b1);
            }
        }
        #pragma unroll
        for (int j = 0; j < 4; j++) {
            int n0 = nh * 32 + j * 8;
            P[(h * 16 + g) * P_STR + n0 + 2*tig]         = acc[j][0] * scale;
            P[(h * 16 + g) * P_STR + n0 + 2*tig + 1]     = acc[j][1] * scale;
            P[(h * 16 + g + 8) * P_STR + n0 + 2*tig]     = acc[j][2] * scale;
            P[(h * 16 + g + 8) * P_STR + n0 + 2*tig + 1] = acc[j][3] * scale;
        }
    }
    __syncthreads();

    // ---- softmax over 64 rows of 64; tf32-rounded writeback ----
    for (int rr = warp; rr < 64; rr += 14) {
        float* row = P + rr * P_STR;
        float a = row[lane], c2 = row[lane + 32];
        float mx = fmaxf(a, c2);
        #pragma unroll
        for (int o = 16; o; o >>= 1) mx = fmaxf(mx, __shfl_xor_sync(~0u, mx, o));
        a = __expf(a - mx); c2 = __expf(c2 - mx);
        float s = a + c2;
        #pragma unroll
        for (int o = 16; o; o >>= 1) s += __shfl_xor_sync(~0u, s, o);
        float inv = 1.f / s;
        row[lane]      = rtf(a * inv);
        row[lane + 32] = rtf(c2 * inv);
    }
    __syncthreads();

    // ---- PV: per head 16x56x64 -> Ot (aliases Qt) ----
    {
        const unsigned* Pb = (const unsigned*)P;
        const unsigned* Vb = (const unsigned*)Vrow;
        #pragma unroll
        for (int ui = 0; ui < 2; ui++) {
            int u = warp * 2 + ui;        // 0..27
            int h = u / 7, j = u - h * 7;
            int n0 = h * 56 + j * 8;
            float acc[4] = {0.f, 0.f, 0.f, 0.f};
            #pragma unroll
            for (int kc = 0; kc < 64; kc += 8) {
                unsigned a0 = Pb[(h * 16 + g) * P_STR + kc + tig];
                unsigned a1 = Pb[(h * 16 + g + 8) * P_STR + kc + tig];
                unsigned a2 = Pb[(h * 16 + g) * P_STR + kc + tig + 4];
                unsigned a3 = Pb[(h * 16 + g + 8) * P_STR + kc + tig + 4];
                unsigned b0 = Vb[(kc + tig) * VR_STR + n0 + g];
                unsigned b1 = Vb[(kc + tig + 4) * VR_STR + n0 + g];
                mma_tf32(acc, a0, a1, a2, a3, b0, b1);
            }
            Ot[g * OT_STR + n0 + 2*tig]           = rtf(acc[0]);
            Ot[g * OT_STR + n0 + 2*tig + 1]       = rtf(acc[1]);
            Ot[(g + 8) * OT_STR + n0 + 2*tig]     = rtf(acc[2]);
            Ot[(g + 8) * OT_STR + n0 + 2*tig + 1] = rtf(acc[3]);
        }
    }
    __syncthreads();

    // ---- attn_proj (16x224x224), accumulate into Rt ----
    {
        const unsigned* Ob = (const unsigned*)Ot;
        int n0w = warp * 16;
        float acc[2][4];
        #pragma unroll
        for (int j = 0; j < 2; j++) {
            int col = n0w + j * 8;
            float bv0 = bp[col + 2 * tig];
            float bv1 = bp[col + 2 * tig + 1];
            acc[j][0] = bv0; acc[j][1] = bv1; acc[j][2] = bv0; acc[j][3] = bv1;
        }
        #pragma unroll 4
        for (int kc = 0; kc < 224; kc += 8) {
            unsigned a0 = Ob[g * OT_STR + kc + tig];
            unsigned a1 = Ob[(g + 8) * OT_STR + kc + tig];
            unsigned a2 = Ob[g * OT_STR + kc + tig + 4];
            unsigned a3 = Ob[(g + 8) * OT_STR + kc + tig + 4];
            #pragma unroll
            for (int j = 0; j < 2; j++) {
                int n0 = n0w + j * 8;
                unsigned b0 = __float_as_uint(g_wpt[(kc + tig) * 224 + n0 + g]);
                unsigned b1 = __float_as_uint(g_wpt[(kc + tig + 4) * 224 + n0 + g]);
                mma_tf32(acc[j], a0, a1, a2, a3, b0, b1);
            }
        }
        #pragma unroll
        for (int j = 0; j < 2; j++) {
            #pragma unroll
            for (int e = 0; e < 4; e++) {
                int q = g + ((e >= 2) ? 8 : 0);
                int d = n0w + j * 8 + 2 * tig + (e & 1);
                Rt[q * RT_STR + d] += acc[j][e];
            }
        }
    }
    __syncthreads();

    // ---- coalesced writeout of hs = residual + proj ----
    for (int e = tid; e < 16 * 56; e += 448) {
        int q = e / 56, c4 = (e - q * 56) * 4;
        int y2 = wy * 4 + (q >> 2), x2 = wx * 4 + (q & 3);
        *(float4*)&g_hs[(((size_t)b * 64 + y2) * 64 + x2) * 224 + c4] =
            *(float4*)&Rt[q * RT_STR + c4];
    }
}

// ---------------------------------------------------------------------------
// K4: out = hs + MLP(LN2(hs)); 512 blocks x 512 threads, 64 tokens/block,
// two hidden-halves of 448 with persistent MLP2 accumulators.
// smem: Xln[64][228] | Ha[64][452]
// ---------------------------------------------------------------------------
#define XLN_STR 228
#define HA_STR  452
#define SMEM4   ((64 * XLN_STR + 64 * HA_STR) * 4)   // 174080 B

__global__ void __launch_bounds__(512) k_mlp(
        const float* __restrict__ g2, const float* __restrict__ b2,
        const float* __restrict__ b1, const float* __restrict__ b2m,
        float* __restrict__ out) {
    extern __shared__ float sm[];
    float* Xln = sm;
    float* Ha  = sm + 64 * XLN_STR;

    int t0   = blockIdx.x * 64;
    int tid  = threadIdx.x;
    int warp = tid >> 5, lane = tid & 31;
    int g = lane >> 2, tig = lane & 3;
    int mt = warp >> 2, ns = warp & 3;

    // ---- LN2 (warp per token) -> Xln tf32 ----
    {
        float gv[7], bv[7];
        #pragma unroll
        for (int k = 0; k < 7; k++) { gv[k] = g2[lane + 32*k]; bv[k] = b2[lane + 32*k]; }
        for (int t = warp; t < 64; t += 16) {
            const float* hr = &g_hs[(size_t)(t0 + t) * 224];
            float v[7]; float s = 0.f;
            #pragma unroll
            for (int k = 0; k < 7; k++) { v[k] = hr[lane + 32*k]; s += v[k]; }
            #pragma unroll
            for (int o = 16; o; o >>= 1) s += __shfl_xor_sync(~0u, s, o);
            float m = s * (1.f / 224.f);
            float q = 0.f;
            #pragma unroll
            for (int k = 0; k < 7; k++) { v[k] -= m; q += v[k] * v[k]; }
            #pragma unroll
            for (int o = 16; o; o >>= 1) q += __shfl_xor_sync(~0u, q, o);
            float rs = rsqrtf(q * (1.f / 224.f) + 1e-6f);
            #pragma unroll
            for (int k = 0; k < 7; k++)
                Xln[t * XLN_STR + lane + 32*k] = rtf(v[k] * rs * gv[k] + bv[k]);
        }
    }
    __syncthreads();

    // persistent MLP2 accumulators
    float acc2[7][4];
    #pragma unroll
    for (int j = 0; j < 7; j++) {
        int col = ns * 56 + j * 8;
        float bv0 = b2m[col + 2 * tig], bv1 = b2m[col + 2 * tig + 1];
        acc2[j][0] = bv0; acc2[j][1] = bv1; acc2[j][2] = bv0; acc2[j][3] = bv1;
    }

    const unsigned* Xb = (const unsigned*)Xln;
    const unsigned* Hb = (const unsigned*)Ha;
    const unsigned* W1 = (const unsigned*)g_w1t;
    const unsigned* W2 = (const unsigned*)g_w2t;

    #pragma unroll 1
    for (int hp = 0; hp < 2; hp++) {
        int hb = hp * 448;
        // MLP1 in two j-sub-passes of 7
        #pragma unroll 1
        for (int jh = 0; jh < 2; jh++) {
            int cb = hb + ns * 112 + jh * 56;
            float acc1[7][4];
            #pragma unroll
            for (int j = 0; j < 7; j++) {
                float bv0 = b1[cb + j * 8 + 2 * tig];
                float bv1 = b1[cb + j * 8 + 2 * tig + 1];
                acc1[j][0] = bv0; acc1[j][1] = bv1; acc1[j][2] = bv0; acc1[j][3] = bv1;
            }
            for (int kc = 0; kc < 224; kc += 8) {
                int r0 = (mt * 16 + g) * XLN_STR + kc;
                int r1 = r0 + 8 * XLN_STR;
                unsigned a0 = Xb[r0 + tig];
                unsigned a1 = Xb[r1 + tig];
                unsigned a2 = Xb[r0 + tig + 4];
                unsigned a3 = Xb[r1 + tig + 4];
                #pragma unroll
                for (int j = 0; j < 7; j++) {
                    int col = cb + j * 8 + g;
                    unsigned w0 = W1[(kc + tig) * 896 + col];
                    unsigned w1 = W1[(kc + tig + 4) * 896 + col];
                    mma_tf32(acc1[j], a0, a1, a2, a3, w0, w1);
                }
            }
            // GELU + store to Ha (local hidden index within this half)
            int lb = ns * 112 + jh * 56;
            #pragma unroll
            for (int j = 0; j < 7; j++) {
                #pragma unroll
                for (int e = 0; e < 4; e++) {
                    int m = mt * 16 + g + ((e >= 2) ? 8 : 0);
                    int lh = lb + j * 8 + 2 * tig + (e & 1);
                    float a = acc1[j][e];
                    Ha[m * HA_STR + lh] = rtf(0.5f * a * (1.f + erff(a * 0.70710678118654752f)));
                }
            }
        }
        __syncthreads();
        // MLP2 partial over this half (K=448)
        for (int kc = 0; kc < 448; kc += 8) {
            int r0 = (mt * 16 + g) * HA_STR + kc;
            int r1 = r0 + 8 * HA_STR;
            unsigned a0 = Hb[r0 + tig];
            unsigned a1 = Hb[r1 + tig];
            unsigned a2 = Hb[r0 + tig + 4];
            unsigned a3 = Hb[r1 + tig + 4];
            #pragma unroll
            for (int j = 0; j < 7; j++) {
                int col = ns * 56 + j * 8 + g;
                unsigned w0 = W2[(hb + kc + tig) * 224 + col];
                unsigned w1 = W2[(hb + kc + tig + 4) * 224 + col];
                mma_tf32(acc2[j], a0, a1, a2, a3, w0, w1);
            }
        }
        __syncthreads();
    }

    // stage MLP output through Xln (dead), then coalesced residual+store
    #pragma unroll
    for (int j = 0; j < 7; j++) {
        #pragma unroll
        for (int e = 0; e < 4; e++) {
            int m = mt * 16 + g + ((e >= 2) ? 8 : 0);
            int n = ns * 56 + j * 8 + 2 * tig + (e & 1);
            Xln[m * XLN_STR + n] = acc2[j][e];
        }
    }
    __syncthreads();
    for (int e = tid; e < 64 * 56; e += 512) {
        int t = e / 56, c4 = (e - t * 56) * 4;
        float4 h = *(const float4*)&g_hs[(size_t)(t0 + t) * 224 + c4];
        float4 a = *(float4*)&Xln[t * XLN_STR + c4];
        *(float4*)&out[(size_t)(t0 + t) * 224 + c4] =
            make_float4(h.x + a.x, h.y + a.y, h.z + a.z, h.w + a.w);
    }
}

// ---------------------------------------------------------------------------
extern "C" void kernel_launch(void* const* d_in, const int* in_sizes, int n_in,
                              void* d_out, int out_size) {
    const float* hidden   = (const float*)d_in[0];
    const float* ln1_g    = (const float*)d_in[1];
    const float* ln1_b    = (const float*)d_in[2];
    const float* qkv_w    = (const float*)d_in[3];
    const float* qkv_b    = (const float*)d_in[4];
    const float* aproj_w  = (const float*)d_in[5];
    const float* aproj_b  = (const float*)d_in[6];
    const float* rproj_w  = (const float*)d_in[7];
    const float* rproj_b  = (const float*)d_in[8];
    const float* ln2_g    = (const float*)d_in[9];
    const float* ln2_b    = (const float*)d_in[10];
    const float* mlp1_w   = (const float*)d_in[11];
    const float* mlp1_b   = (const float*)d_in[12];
    const float* mlp2_w   = (const float*)d_in[13];
    const float* mlp2_b   = (const float*)d_in[14];
    float* out = (float*)d_out;

    cudaFuncSetAttribute(k_attn, cudaFuncAttributeMaxDynamicSharedMemorySize, SMEM3);
    cudaFuncSetAttribute(k_mlp,  cudaFuncAttributeMaxDynamicSharedMemorySize, SMEM4);

    k_prep<<<196, 1024>>>(mlp1_w, mlp2_w, qkv_w, rproj_w, aproj_w, qkv_b, rproj_b);
    k_attn<<<2048, 448, SMEM3>>>(hidden, ln1_g, ln1_b, aproj_b);
    k_mlp<<<512, 512, SMEM4>>>(ln2_g, ln2_b, mlp1_b, mlp2_b, out);
}

// round 6
// speedup vs baseline: 5.7099x; 1.2605x over previous
#include <cuda_runtime.h>
#include <math.h>

#define NTOK  (8*64*64)

// Scratch (device globals)
__device__ float g_hs[(size_t)NTOK * 224];   // residual + attn output
__device__ float g_w1t[224 * 896];           // tf32 mlp1_w
__device__ float g_w2t[896 * 224];           // tf32 mlp2_w
__device__ float g_wbig[112 * 896];          // tf32 [qkv_w | res_proj_w]
__device__ float g_wpt[224 * 224];           // tf32 attn_proj_w
__device__ float g_bbig[896];                // [qkv_b | res_proj_b]

__device__ __forceinline__ unsigned f2tf32(float x) {
    unsigned r;
    asm("cvt.rna.tf32.f32 %0, %1;" : "=r"(r) : "f"(x));
    return r;
}
__device__ __forceinline__ float rtf(float x) { return __uint_as_float(f2tf32(x)); }

__device__ __forceinline__ void mma_tf32(float* c,
        unsigned a0, unsigned a1, unsigned a2, unsigned a3,
        unsigned b0, unsigned b1) {
    asm("mma.sync.aligned.m16n8k8.row.col.f32.tf32.tf32.f32 "
        "{%0,%1,%2,%3}, {%4,%5,%6,%7}, {%8,%9}, {%0,%1,%2,%3};"
        : "+f"(c[0]), "+f"(c[1]), "+f"(c[2]), "+f"(c[3])
        : "r"(a0), "r"(a1), "r"(a2), "r"(a3), "r"(b0), "r"(b1));
}

// ---------------------------------------------------------------------------
// K0: round weights to tf32, build combined [qkv|res] weight + bias
// ---------------------------------------------------------------------------
__global__ void k_prep(const float* __restrict__ W1,   const float* __restrict__ W2,
                       const float* __restrict__ Wqkv, const float* __restrict__ Wrp,
                       const float* __restrict__ Wp,
                       const float* __restrict__ bqkv, const float* __restrict__ brp) {
    int i = blockIdx.x * 1024 + threadIdx.x;
    if (i < 224 * 896) { g_w1t[i] = rtf(W1[i]); g_w2t[i] = rtf(W2[i]); }
    if (i < 112 * 896) {
        int r = i / 896, c = i - r * 896;
        float v = (c < 672) ? Wqkv[r * 672 + c] : Wrp[r * 224 + (c - 672)];
        g_wbig[i] = rtf(v);
    }
    if (i < 224 * 224) g_wpt[i] = rtf(Wp[i]);
    if (i < 896) g_bbig[i] = (i < 672) ? bqkv[i] : brp[i - 672];
}

// ---------------------------------------------------------------------------
// K3: fused LN1 + QKV/R GEMM + pooling + attention + proj + residual
// 2048 blocks x 448 threads (14 warps)
// smem: Xs[64][116] | Kt[224][72] | Vrow[64][232] | Qt[16][236] | Rt[16][236]
// P (64x76) aliases Xs; Ot (16x236) aliases Qt.
// ---------------------------------------------------------------------------
#define XS_STR 116
#define KT_STR 72
#define VR_STR 232
#define QT_STR 236
#define RT_STR 236
#define OT_STR 236
#define P_STR  76
#define XS_N (64 * XS_STR)     // 7424
#define KT_N (224 * KT_STR)    // 16128
#define VR_N (64 * VR_STR)     // 14848
#define QT_N (16 * QT_STR)     // 3776
#define RT_N (16 * RT_STR)     // 3776
#define SMEM3 ((XS_N + KT_N + VR_N + QT_N + RT_N) * 4)   // 183808 B

__global__ void __launch_bounds__(448) k_attn(
        const float* __restrict__ hidden,
        const float* __restrict__ ln1g, const float* __restrict__ ln1b,
        const float* __restrict__ bp) {
    extern __shared__ float sm[];
    float* Xs   = sm;
    float* Kt   = Xs + XS_N;
    float* Vrow = Kt + KT_N;
    float* Qt   = Vrow + VR_N;
    float* Rt   = Qt + QT_N;
    float* P    = Xs;    // alias (X dead after QKV)
    float* Ot   = Qt;    // alias (Qt dead after scores)

    int wi = blockIdx.x;
    int b  = wi >> 8;
    int r  = wi & 255;
    int wy = r >> 4, wx = r & 15;
    int tid  = threadIdx.x;
    int warp = tid >> 5, lane = tid & 31;
    int g = lane >> 2, tig = lane & 3;

    // ---- stage raw window ----
    for (int e = tid; e < 64 * 28; e += 448) {
        int t = e / 28, c4 = (e - t * 28) * 4;
        int y = wy * 8 + (t >> 3), x = wx * 8 + (t & 7);
        *(float4*)&Xs[t * XS_STR + c4] =
            *(const float4*)&hidden[(((size_t)b * 128 + y) * 128 + x) * 112 + c4];
    }
    __syncthreads();

    // ---- LN1 in place (warp per token), tf32-rounded ----
    {
        float gg0 = ln1g[lane], gg1 = ln1g[lane + 32], gg2 = ln1g[lane + 64];
        float bb0 = ln1b[lane], bb1 = ln1b[lane + 32], bb2 = ln1b[lane + 64];
        float gg3 = 0.f, bb3 = 0.f;
        if (lane < 16) { gg3 = ln1g[lane + 96]; bb3 = ln1b[lane + 96]; }
        for (int t = warp; t < 64; t += 14) {
            float* row = Xs + t * XS_STR;
            float v0 = row[lane], v1 = row[lane + 32], v2 = row[lane + 64];
            float v3 = (lane < 16) ? row[lane + 96] : 0.f;
            float s = v0 + v1 + v2 + v3;
            #pragma unroll
            for (int o = 16; o; o >>= 1) s += __shfl_xor_sync(~0u, s, o);
            float m = s * (1.f / 112.f);
            float d0 = v0 - m, d1 = v1 - m, d2 = v2 - m;
            float d3 = (lane < 16) ? v3 - m : 0.f;
            float q = d0*d0 + d1*d1 + d2*d2 + d3*d3;
            #pragma unroll
            for (int o = 16; o; o >>= 1) q += __shfl_xor_sync(~0u, q, o);
            float rs = rsqrtf(q * (1.f / 112.f) + 1e-6f);
            row[lane]      = rtf(d0 * rs * gg0 + bb0);
            row[lane + 32] = rtf(d1 * rs * gg1 + bb1);
            row[lane + 64] = rtf(d2 * rs * gg2 + bb2);
            if (lane < 16) row[lane + 96] = rtf(d3 * rs * gg3 + bb3);
        }
    }
    __syncthreads();

    // ---- QKV+R GEMM: M=64, N=896, K=112; warp n-slice 64, two j-passes of 4 ----
    {
        const unsigned* Xb = (const unsigned*)Xs;
        const unsigned* Wb = (const unsigned*)g_wbig;
        #pragma unroll
        for (int pass = 0; pass < 2; pass++) {
            int colbase = warp * 64 + pass * 32;
            float acc[4][4][4];
            #pragma unroll
            for (int j = 0; j < 4; j++) {
                int col = colbase + j * 8;
                float bv0 = g_bbig[col + 2 * tig];
                float bv1 = g_bbig[col + 2 * tig + 1];
                #pragma unroll
                for (int mt = 0; mt < 4; mt++) {
                    acc[mt][j][0] = bv0; acc[mt][j][1] = bv1;
                    acc[mt][j][2] = bv0; acc[mt][j][3] = bv1;
                }
            }
            for (int kc = 0; kc < 112; kc += 8) {
                unsigned a[4][4];
                #pragma unroll
                for (int mt = 0; mt < 4; mt++) {
                    int r0 = (mt * 16 + g) * XS_STR + kc;
                    int r1 = r0 + 8 * XS_STR;
                    a[mt][0] = Xb[r0 + tig];
                    a[mt][1] = Xb[r1 + tig];
                    a[mt][2] = Xb[r0 + tig + 4];
                    a[mt][3] = Xb[r1 + tig + 4];
                }
                #pragma unroll
                for (int j = 0; j < 4; j++) {
                    int col = colbase + j * 8 + g;
                    unsigned b0 = Wb[(kc + tig) * 896 + col];
                    unsigned b1 = Wb[(kc + tig + 4) * 896 + col];
                    #pragma unroll
                    for (int mt = 0; mt < 4; mt++)
                        mma_tf32(acc[mt][j], a[mt][0], a[mt][1], a[mt][2], a[mt][3], b0, b1);
                }
            }
            // routed stores (uniform branch per warp/j)
            #pragma unroll
            for (int j = 0; j < 4; j++) {
                int col = colbase + j * 8;
                int mat = col / 224;
                int lc  = col - mat * 224;
                if (mat == 1) {            // K -> Kt[d][t]  (scalar: transpose)
                    #pragma unroll
                    for (int mt = 0; mt < 4; mt++) {
                        int t0r = mt * 16 + g;
                        Kt[(lc + 2*tig)     * KT_STR + t0r]     = rtf(acc[mt][j][0]);
                        Kt[(lc + 2*tig + 1) * KT_STR + t0r]     = rtf(acc[mt][j][1]);
                        Kt[(lc + 2*tig)     * KT_STR + t0r + 8] = rtf(acc[mt][j][2]);
                        Kt[(lc + 2*tig + 1) * KT_STR + t0r + 8] = rtf(acc[mt][j][3]);
                    }
                } else if (mat == 2) {     // V -> Vrow[t][d]  (float2)
                    #pragma unroll
                    for (int mt = 0; mt < 4; mt++) {
                        int t0r = mt * 16 + g;
                        *(float2*)&Vrow[t0r * VR_STR + lc + 2*tig] =
                            make_float2(rtf(acc[mt][j][0]), rtf(acc[mt][j][1]));
                        *(float2*)&Vrow[(t0r + 8) * VR_STR + lc + 2*tig] =
                            make_float2(rtf(acc[mt][j][2]), rtf(acc[mt][j][3]));
                    }
                } else {                   // Q (mat 0) or R (mat 3): 2x2 pool in regs
                    #pragma unroll
                    for (int mt = 0; mt < 4; mt++) {
                        float m0 = fmaxf(acc[mt][j][0], acc[mt][j][2]);  // rows g, g+8
                        float m1 = fmaxf(acc[mt][j][1], acc[mt][j][3]);
                        m0 = fmaxf(m0, __shfl_xor_sync(~0u, m0, 4));     // lanes g ^ 1
                        m1 = fmaxf(m1, __shfl_xor_sync(~0u, m1, 4));
                        if (!(g & 1)) {
                            int q = mt * 4 + (g >> 1);
                            if (mat == 0)
                                *(float2*)&Qt[q * QT_STR + lc + 2*tig] =
                                    make_float2(rtf(m0), rtf(m1));
                            else
                                *(float2*)&Rt[q * RT_STR + lc + 2*tig] =
                                    make_float2(m0, m1);
                        }
                    }
                }
            }
        }
    }
    __syncthreads();

    // ---- scores: per head 16x64x56 -> P (aliases Xs) ----
    const float scale = 0.13363062095621219f;   // 56^-0.5
    if (warp < 8) {
        int h = warp >> 1, nh = warp & 1;
        const unsigned* Qb = (const unsigned*)Qt;
        const unsigned* Kb = (const unsigned*)Kt;
        float acc[4][4];
        #pragma unroll
        for (int j = 0; j < 4; j++)
            #pragma unroll
            for (int e = 0; e < 4; e++) acc[j][e] = 0.f;
        #pragma unroll
        for (int kc = 0; kc < 56; kc += 8) {
            int kd = h * 56 + kc;
            unsigned a0 = Qb[g * QT_STR + kd + tig];
            unsigned a1 = Qb[(g + 8) * QT_STR + kd + tig];
            unsigned a2 = Qb[g * QT_STR + kd + tig + 4];
            unsigned a3 = Qb[(g + 8) * QT_STR + kd + tig + 4];
            #pragma unroll
            for (int j = 0; j < 4; j++) {
                int n0 = nh * 32 + j * 8;
                unsigned b0 = Kb[(kd + tig) * KT_STR + n0 + g];
                unsigned b1 = Kb[(kd + tig + 4) * KT_STR + n0 + g];
                mma_tf32(acc[j], a0, a1, a2, a3, b0, b1);
            }
        }
        #pragma unroll
        for (int j = 0; j < 4; j++) {
            int n0 = nh * 32 + j * 8;
            *(float2*)&P[(h * 16 + g) * P_STR + n0 + 2*tig] =
                make_float2(acc[j][0] * scale, acc[j][1] * scale);
            *(float2*)&P[(h * 16 + g + 8) * P_STR + n0 + 2*tig] =
                make_float2(acc[j][2] * scale, acc[j][3] * scale);
        }
    }
    __syncthreads();

    // ---- softmax over 64 rows of 64; tf32-rounded writeback ----
    for (int rr = warp; rr < 64; rr += 14) {
        float* row = P + rr * P_STR;
        float a = row[lane], c2 = row[lane + 32];
        float mx = fmaxf(a, c2);
        #pragma unroll
        for (int o = 16; o; o >>= 1) mx = fmaxf(mx, __shfl_xor_sync(~0u, mx, o));
        a = __expf(a - mx); c2 = __expf(c2 - mx);
        float s = a + c2;
        #pragma unroll
        for (int o = 16; o; o >>= 1) s += __shfl_xor_sync(~0u, s, o);
        float inv = 1.f / s;
        row[lane]      = rtf(a * inv);
        row[lane + 32] = rtf(c2 * inv);
    }
    __syncthreads();

    // ---- PV: per head 16x56x64 -> Ot (aliases Qt) ----
    {
        const unsigned* Pb = (const unsigned*)P;
        const unsigned* Vb = (const unsigned*)Vrow;
        #pragma unroll
        for (int ui = 0; ui < 2; ui++) {
            int u = warp * 2 + ui;        // 0..27
            int h = u / 7, j = u - h * 7;
            int n0 = h * 56 + j * 8;
            float acc[4] = {0.f, 0.f, 0.f, 0.f};
            #pragma unroll
            for (int kc = 0; kc < 64; kc += 8) {
                unsigned a0 = Pb[(h * 16 + g) * P_STR + kc + tig];
                unsigned a1 = Pb[(h * 16 + g + 8) * P_STR + kc + tig];
                unsigned a2 = Pb[(h * 16 + g) * P_STR + kc + tig + 4];
                unsigned a3 = Pb[(h * 16 + g + 8) * P_STR + kc + tig + 4];
                unsigned b0 = Vb[(kc + tig) * VR_STR + n0 + g];
                unsigned b1 = Vb[(kc + tig + 4) * VR_STR + n0 + g];
                mma_tf32(acc, a0, a1, a2, a3, b0, b1);
            }
            *(float2*)&Ot[g * OT_STR + n0 + 2*tig] =
                make_float2(rtf(acc[0]), rtf(acc[1]));
            *(float2*)&Ot[(g + 8) * OT_STR + n0 + 2*tig] =
                make_float2(rtf(acc[2]), rtf(acc[3]));
        }
    }
    __syncthreads();

    // ---- attn_proj (16x224x224), accumulate into Rt ----
    {
        const unsigned* Ob = (const unsigned*)Ot;
        int n0w = warp * 16;
        float acc[2][4];
        #pragma unroll
        for (int j = 0; j < 2; j++) {
            int col = n0w + j * 8;
            float bv0 = bp[col + 2 * tig];
            float bv1 = bp[col + 2 * tig + 1];
            acc[j][0] = bv0; acc[j][1] = bv1; acc[j][2] = bv0; acc[j][3] = bv1;
        }
        #pragma unroll 4
        for (int kc = 0; kc < 224; kc += 8) {
            unsigned a0 = Ob[g * OT_STR + kc + tig];
            unsigned a1 = Ob[(g + 8) * OT_STR + kc + tig];
            unsigned a2 = Ob[g * OT_STR + kc + tig + 4];
            unsigned a3 = Ob[(g + 8) * OT_STR + kc + tig + 4];
            #pragma unroll
            for (int j = 0; j < 2; j++) {
                int n0 = n0w + j * 8;
                unsigned b0 = __float_as_uint(g_wpt[(kc + tig) * 224 + n0 + g]);
                unsigned b1 = __float_as_uint(g_wpt[(kc + tig + 4) * 224 + n0 + g]);
                mma_tf32(acc[j], a0, a1, a2, a3, b0, b1);
            }
        }
        #pragma unroll
        for (int j = 0; j < 2; j++) {
            int d = n0w + j * 8 + 2 * tig;
            float2 r0v = *(float2*)&Rt[g * RT_STR + d];
            *(float2*)&Rt[g * RT_STR + d] =
                make_float2(r0v.x + acc[j][0], r0v.y + acc[j][1]);
            float2 r1v = *(float2*)&Rt[(g + 8) * RT_STR + d];
            *(float2*)&Rt[(g + 8) * RT_STR + d] =
                make_float2(r1v.x + acc[j][2], r1v.y + acc[j][3]);
        }
    }
    __syncthreads();

    // ---- coalesced writeout of hs = residual + proj ----
    for (int e = tid; e < 16 * 56; e += 448) {
        int q = e / 56, c4 = (e - q * 56) * 4;
        int y2 = wy * 4 + (q >> 2), x2 = wx * 4 + (q & 3);
        *(float4*)&g_hs[(((size_t)b * 64 + y2) * 64 + x2) * 224 + c4] =
            *(float4*)&Rt[q * RT_STR + c4];
    }
}

// ---------------------------------------------------------------------------
// K4: out = hs + MLP(LN2(hs)); 512 blocks x 448 threads (14 warps),
// 64 tokens/block; warp spans all 4 m-tiles for 4x B-reuse.
// Two hidden-halves of 448 with persistent MLP2 accumulators.
// smem: Xln[64][228] | Ha[64][452]
// ---------------------------------------------------------------------------
#define XLN_STR 228
#define HA_STR  452
#define SMEM4   ((64 * XLN_STR + 64 * HA_STR) * 4)   // 174080 B

__global__ void __launch_bounds__(448) k_mlp(
        const float* __restrict__ g2, const float* __restrict__ b2,
        const float* __restrict__ b1, const float* __restrict__ b2m,
        float* __restrict__ out) {
    extern __shared__ float sm[];
    float* Xln = sm;
    float* Ha  = sm + 64 * XLN_STR;

    int t0   = blockIdx.x * 64;
    int tid  = threadIdx.x;
    int warp = tid >> 5, lane = tid & 31;
    int g = lane >> 2, tig = lane & 3;

    // ---- LN2 (warp per token) -> Xln tf32 ----
    {
        float gv[7], bv[7];
        #pragma unroll
        for (int k = 0; k < 7; k++) { gv[k] = g2[lane + 32*k]; bv[k] = b2[lane + 32*k]; }
        for (int t = warp; t < 64; t += 14) {
            const float* hr = &g_hs[(size_t)(t0 + t) * 224];
            float v[7]; float s = 0.f;
            #pragma unroll
            for (int k = 0; k < 7; k++) { v[k] = hr[lane + 32*k]; s += v[k]; }
            #pragma unroll
            for (int o = 16; o; o >>= 1) s += __shfl_xor_sync(~0u, s, o);
            float m = s * (1.f / 224.f);
            float q = 0.f;
            #pragma unroll
            for (int k = 0; k < 7; k++) { v[k] -= m; q += v[k] * v[k]; }
            #pragma unroll
            for (int o = 16; o; o >>= 1) q += __shfl_xor_sync(~0u, q, o);
            float rs = rsqrtf(q * (1.f / 224.f) + 1e-6f);
            #pragma unroll
            for (int k = 0; k < 7; k++)
                Xln[t * XLN_STR + lane + 32*k] = rtf(v[k] * rs * gv[k] + bv[k]);
        }
    }
    __syncthreads();

    const unsigned* Xb = (const unsigned*)Xln;
    const unsigned* Hb = (const unsigned*)Ha;
    const unsigned* W1 = (const unsigned*)g_w1t;
    const unsigned* W2 = (const unsigned*)g_w2t;

    // persistent MLP2 accumulators: warp owns n-cols [warp*16, warp*16+16)
    int n0w = warp * 16;
    float acc2[4][2][4];
    #pragma unroll
    for (int j = 0; j < 2; j++) {
        float bv0 = b2m[n0w + j * 8 + 2 * tig];
        float bv1 = b2m[n0w + j * 8 + 2 * tig + 1];
        #pragma unroll
        for (int mt = 0; mt < 4; mt++) {
            acc2[mt][j][0] = bv0; acc2[mt][j][1] = bv1;
            acc2[mt][j][2] = bv0; acc2[mt][j][3] = bv1;
        }
    }

    #pragma unroll 1
    for (int hp = 0; hp < 2; hp++) {
        int hb = hp * 448;
        // ---- MLP1: warp cols = hb + warp*32 .. +32, all 64 rows ----
        {
            int cb = hb + warp * 32;
            float acc1[4][4][4];
            #pragma unroll
            for (int j = 0; j < 4; j++) {
                float bv0 = b1[cb + j * 8 + 2 * tig];
                float bv1 = b1[cb + j * 8 + 2 * tig + 1];
                #pragma unroll
                for (int mt = 0; mt < 4; mt++) {
                    acc1[mt][j][0] = bv0; acc1[mt][j][1] = bv1;
                    acc1[mt][j][2] = bv0; acc1[mt][j][3] = bv1;
                }
            }
            for (int kc = 0; kc < 224; kc += 8) {
                unsigned a[4][4];
                #pragma unroll
                for (int mt = 0; mt < 4; mt++) {
                    int r0 = (mt * 16 + g) * XLN_STR + kc;
                    int r1 = r0 + 8 * XLN_STR;
                    a[mt][0] = Xb[r0 + tig];
                    a[mt][1] = Xb[r1 + tig];
                    a[mt][2] = Xb[r0 + tig + 4];
                    a[mt][3] = Xb[r1 + tig + 4];
                }
                #pragma unroll
                for (int j = 0; j < 4; j++) {
                    int col = cb + j * 8 + g;
                    unsigned w0 = W1[(kc + tig) * 896 + col];
                    unsigned w1 = W1[(kc + tig + 4) * 896 + col];
                    #pragma unroll
                    for (int mt = 0; mt < 4; mt++)
                        mma_tf32(acc1[mt][j], a[mt][0], a[mt][1], a[mt][2], a[mt][3], w0, w1);
                }
            }
            // GELU -> Ha (local hidden index within half)
            int lb = warp * 32;
            #pragma unroll
            for (int mt = 0; mt < 4; mt++)
                #pragma unroll
                for (int j = 0; j < 4; j++) {
                    int lh = lb + j * 8 + 2 * tig;
                    int m0 = mt * 16 + g;
                    float a0 = acc1[mt][j][0], a1 = acc1[mt][j][1];
                    float a2 = acc1[mt][j][2], a3 = acc1[mt][j][3];
                    *(float2*)&Ha[m0 * HA_STR + lh] = make_float2(
                        rtf(0.5f * a0 * (1.f + erff(a0 * 0.70710678118654752f))),
                        rtf(0.5f * a1 * (1.f + erff(a1 * 0.70710678118654752f))));
                    *(float2*)&Ha[(m0 + 8) * HA_STR + lh] = make_float2(
                        rtf(0.5f * a2 * (1.f + erff(a2 * 0.70710678118654752f))),
                        rtf(0.5f * a3 * (1.f + erff(a3 * 0.70710678118654752f))));
                }
        }
        __syncthreads();
        // ---- MLP2 partial over this half (K=448) ----
        for (int kc = 0; kc < 448; kc += 8) {
            unsigned a[4][4];
            #pragma unroll
            for (int mt = 0; mt < 4; mt++) {
                int r0 = (mt * 16 + g) * HA_STR + kc;
                int r1 = r0 + 8 * HA_STR;
                a[mt][0] = Hb[r0 + tig];
                a[mt][1] = Hb[r1 + tig];
                a[mt][2] = Hb[r0 + tig + 4];
                a[mt][3] = Hb[r1 + tig + 4];
            }
            #pragma unroll
            for (int j = 0; j < 2; j++) {
                int col = n0w + j * 8 + g;
                unsigned w0 = W2[(hb + kc + tig) * 224 + col];
                unsigned w1 = W2[(hb + kc + tig + 4) * 224 + col];
                #pragma unroll
                for (int mt = 0; mt < 4; mt++)
                    mma_tf32(acc2[mt][j], a[mt][0], a[mt][1], a[mt][2], a[mt][3], w0, w1);
            }
        }
        __syncthreads();
    }

    // ---- epilogue: residual + direct store (float2, 32B row segments) ----
    #pragma unroll
    for (int mt = 0; mt < 4; mt++)
        #pragma unroll
        for (int j = 0; j < 2; j++) {
            int n = n0w + j * 8 + 2 * tig;
            int m0 = t0 + mt * 16 + g;
            float2 h0 = *(const float2*)&g_hs[(size_t)m0 * 224 + n];
            *(float2*)&out[(size_t)m0 * 224 + n] =
                make_float2(h0.x + acc2[mt][j][0], h0.y + acc2[mt][j][1]);
            float2 h1 = *(const float2*)&g_hs[(size_t)(m0 + 8) * 224 + n];
            *(float2*)&out[(size_t)(m0 + 8) * 224 + n] =
                make_float2(h1.x + acc2[mt][j][2], h1.y + acc2[mt][j][3]);
        }
}

// ---------------------------------------------------------------------------
extern "C" void kernel_launch(void* const* d_in, const int* in_sizes, int n_in,
                              void* d_out, int out_size) {
    const float* hidden   = (const float*)d_in[0];
    const float* ln1_g    = (const float*)d_in[1];
    const float* ln1_b    = (const float*)d_in[2];
    const float* qkv_w    = (const float*)d_in[3];
    const float* qkv_b    = (const float*)d_in[4];
    const float* aproj_w  = (const float*)d_in[5];
    const float* aproj_b  = (const float*)d_in[6];
    const float* rproj_w  = (const float*)d_in[7];
    const float* rproj_b  = (const float*)d_in[8];
    const float* ln2_g    = (const float*)d_in[9];
    const float* ln2_b    = (const float*)d_in[10];
    const float* mlp1_w   = (const float*)d_in[11];
    const float* mlp1_b   = (const float*)d_in[12];
    const float* mlp2_w   = (const float*)d_in[13];
    const float* mlp2_b   = (const float*)d_in[14];
    float* out = (float*)d_out;

    cudaFuncSetAttribute(k_attn, cudaFuncAttributeMaxDynamicSharedMemorySize, SMEM3);
    cudaFuncSetAttribute(k_mlp,  cudaFuncAttributeMaxDynamicSharedMemorySize, SMEM4);

    k_prep<<<196, 1024>>>(mlp1_w, mlp2_w, qkv_w, rproj_w, aproj_w, qkv_b, rproj_b);
    k_attn<<<2048, 448, SMEM3>>>(hidden, ln1_g, ln1_b, aproj_b);
    k_mlp<<<512, 448, SMEM4>>>(ln2_g, ln2_b, mlp1_b, mlp2_b, out);
}